// round 2
// baseline (speedup 1.0000x reference)
#include <cuda_runtime.h>
#include <math.h>

#define B_    4
#define L_    2048
#define KNN   30
#define NNODE (B_*L_)          /* 8192   */
#define NEDGE (NNODE*KNN)      /* 245760 */
#define SIN_LD 264             /* padded row stride for s_in (263 features) */

/* ------------------------------------------------------------------ */
/* static device scratch (no runtime allocation allowed)               */
/* ------------------------------------------------------------------ */
__device__ float g_M[768];                          /* wh @ wv  (3 x 256) */
__device__ float g_sin[(size_t)NNODE * SIN_LD];     /* GVP scalar input   */
__device__ float g_spre[(size_t)NNODE * 1024];      /* pre-LN scalar out  */
__device__ unsigned char g_mask[NNODE];             /* expanded coord_mask */

struct F3 { float x, y, z; };
__device__ __forceinline__ F3 mkf3(float x, float y, float z){ F3 r; r.x=x; r.y=y; r.z=z; return r; }
__device__ __forceinline__ F3 sub3(F3 a, F3 b){ return mkf3(a.x-b.x, a.y-b.y, a.z-b.z); }
__device__ __forceinline__ F3 add3(F3 a, F3 b){ return mkf3(a.x+b.x, a.y+b.y, a.z+b.z); }
__device__ __forceinline__ float dot3(F3 a, F3 b){ return a.x*b.x + a.y*b.y + a.z*b.z; }
__device__ __forceinline__ F3 cross3(F3 a, F3 b){
    return mkf3(a.y*b.z - a.z*b.y, a.z*b.x - a.x*b.z, a.x*b.y - a.y*b.x);
}
/* JAX _normalize: t / sqrt(sum(t*t) + 1e-8) */
__device__ __forceinline__ F3 norml(F3 a){
    float n = sqrtf(dot3(a,a) + 1e-8f);
    return mkf3(a.x/n, a.y/n, a.z/n);
}
__device__ __forceinline__ unsigned long long umin64(unsigned long long a, unsigned long long b){
    return a < b ? a : b;
}

/* ------------------------------------------------------------------ */
/* kernel -1: detect bool storage layout and expand coord_mask         */
/* byte mode: nonzero bytes at pos%4!=0; int32: nonzero only at %4==0  */
/* (and some at %8==4); int64: nonzero only at %8==0.                  */
/* ------------------------------------------------------------------ */
__global__ void mask_prep_kernel(const unsigned char* __restrict__ mraw){
    __shared__ int sA, sB;
    int tid = threadIdx.x;
    if (tid == 0){ sA = 0; sB = 0; }
    __syncthreads();
    int la = 0, lb = 0;
    for (int i = tid; i < 8192; i += 1024){
        unsigned char v = mraw[i];
        if (v){
            if (i & 3) la++;
            else if ((i & 7) == 4) lb++;
        }
    }
    if (la) atomicAdd(&sA, la);
    if (lb) atomicAdd(&sB, lb);
    __syncthreads();
    int mode = (sA > 0) ? 0 : ((sB > 0) ? 1 : 2);   /* 0=byte 1=i32 2=i64 */
    for (int i = tid; i < NNODE; i += 1024){
        unsigned char v;
        if (mode == 0)      v = mraw[i] ? 1 : 0;
        else if (mode == 1) v = ((const int*)mraw)[i] ? 1 : 0;
        else                v = ((const long long*)mraw)[i] ? 1 : 0;
        g_mask[i] = v;
    }
}

/* ------------------------------------------------------------------ */
/* kernel 0: M = wh @ wv   (3x256 @ 256x256)                            */
/* ------------------------------------------------------------------ */
__global__ void prep_M_kernel(const float* __restrict__ wh, const float* __restrict__ wv){
    int v = threadIdx.x;            /* 0..255 */
    #pragma unroll
    for (int i = 0; i < 3; i++){
        float s = 0.f;
        for (int h = 0; h < 256; h++) s += wh[i*256 + h] * wv[h*256 + v];
        g_M[i*256 + v] = s;
    }
}

/* ------------------------------------------------------------------ */
/* kernel 1: node features + GVP vector path + vector layernorm        */
/* one block (256 threads) per node                                    */
/* ------------------------------------------------------------------ */
__device__ __forceinline__ F3 ldatom(const float* Cb, int r, int a){
    const float* p = Cb + ((size_t)r*3 + a)*3;
    return mkf3(p[0], p[1], p[2]);
}

__global__ void node_feat_kernel(const float* __restrict__ coords,
                                 const float* __restrict__ wh,
                                 float* __restrict__ nv_out)
{
    int nid = blockIdx.x;
    int b = nid / L_, i = nid % L_;
    int tid = threadIdx.x;

    __shared__ float sh_v[9];     /* v0=f, v1=bk, v2=sidechain */
    __shared__ float sh_s7[7];
    __shared__ float sh_red[8];
    __shared__ float sh_denom;

    if (tid == 0){
        const float* Cb = coords + (size_t)b * L_ * 9;
        F3 xca = ldatom(Cb, i, 1);
        /* orientations */
        F3 fwd = mkf3(0.f,0.f,0.f), bk = mkf3(0.f,0.f,0.f);
        if (i < L_-1) fwd = norml(sub3(ldatom(Cb, i+1, 1), xca));
        if (i > 0)    bk  = norml(sub3(ldatom(Cb, i-1, 1), xca));
        /* sidechain */
        F3 nn = norml(sub3(ldatom(Cb, i, 0), xca));
        F3 cc = norml(sub3(ldatom(Cb, i, 2), xca));
        F3 bis  = norml(add3(cc, nn));
        F3 perp = norml(cross3(cc, nn));
        const float k1 = 0.5773502691896258f;   /* sqrt(1/3) */
        const float k2 = 0.8164965809277260f;   /* sqrt(2/3) */
        F3 sc = mkf3(-bis.x*k1 - perp.x*k2, -bis.y*k1 - perp.y*k2, -bis.z*k1 - perp.z*k2);
        sh_v[0]=fwd.x; sh_v[1]=fwd.y; sh_v[2]=fwd.z;
        sh_v[3]=bk.x;  sh_v[4]=bk.y;  sh_v[5]=bk.z;
        sh_v[6]=sc.x;  sh_v[7]=sc.y;  sh_v[8]=sc.z;

        /* dihedrals: need U[3i-1 .. 3i+3], Xf[t]=coords[b][t/3][t%3] */
        F3 U[5];
        #pragma unroll
        for (int a = 0; a < 5; a++){
            int t = 3*i - 1 + a;
            if (t >= 0 && t <= 3*L_ - 2){
                F3 p0 = ldatom(Cb, t/3, t%3);
                int t1 = t + 1;
                F3 p1 = ldatom(Cb, t1/3, t1%3);
                U[a] = norml(sub3(p1, p0));
            } else U[a] = mkf3(0.f,0.f,0.f);
        }
        #pragma unroll
        for (int a = 0; a < 3; a++){
            int t = 3*i - 1 + a;
            float D = 0.f;
            if (t >= 0 && t <= 3*L_ - 4){
                F3 u2 = U[a], u1 = U[a+1], u0 = U[a+2];
                F3 n2 = norml(cross3(u2, u1));
                F3 n1 = norml(cross3(u1, u0));
                float cd = dot3(n2, n1);
                cd = fminf(fmaxf(cd, -1.f + 1e-7f), 1.f - 1e-7f);
                float sg = dot3(u2, n1);
                float s = (sg > 0.f) ? 1.f : ((sg < 0.f) ? -1.f : 0.f);
                D = s * acosf(cd);
            }
            sh_s7[a]   = cosf(D);
            sh_s7[3+a] = sinf(D);
        }
        sh_s7[6] = g_mask[nid] ? 1.f : 0.f;
    }
    __syncthreads();

    F3 v0 = mkf3(sh_v[0], sh_v[1], sh_v[2]);
    F3 v1 = mkf3(sh_v[3], sh_v[4], sh_v[5]);
    F3 v2 = mkf3(sh_v[6], sh_v[7], sh_v[8]);

    int h = tid;
    float w0 = wh[h], w1 = wh[256+h], w2 = wh[512+h];
    F3 vh = mkf3(v0.x*w0 + v1.x*w1 + v2.x*w2,
                 v0.y*w0 + v1.y*w1 + v2.y*w2,
                 v0.z*w0 + v1.z*w1 + v2.z*w2);
    float vn = sqrtf(fmaxf(dot3(vh,vh), 1e-8f));
    g_sin[(size_t)nid*SIN_LD + 7 + h] = vn;
    if (tid < 7) g_sin[(size_t)nid*SIN_LD + tid] = sh_s7[tid];

    float m0 = g_M[h], m1 = g_M[256+h], m2 = g_M[512+h];
    F3 vo = mkf3(v0.x*m0 + v1.x*m1 + v2.x*m2,
                 v0.y*m0 + v1.y*m1 + v2.y*m2,
                 v0.z*m0 + v1.z*m1 + v2.z*m2);
    float c = fmaxf(dot3(vo,vo), 1e-8f);
    #pragma unroll
    for (int o = 16; o; o >>= 1) c += __shfl_down_sync(0xffffffffu, c, o);
    if ((tid & 31) == 0) sh_red[tid >> 5] = c;
    __syncthreads();
    if (tid == 0){
        float s = 0.f;
        #pragma unroll
        for (int w = 0; w < 8; w++) s += sh_red[w];
        sh_denom = sqrtf(s * (1.f/256.f));
    }
    __syncthreads();
    float dn = sh_denom;
    float* o = nv_out + (size_t)nid*768 + (size_t)h*3;
    o[0] = vo.x/dn; o[1] = vo.y/dn; o[2] = vo.z/dn;
}

/* ------------------------------------------------------------------ */
/* kernel 2: SGEMM  C[8192,1024] = A[8192,263] @ B[263,1024] + bias    */
/* 128x128 tile, BK=8, 256 threads, 8x8 per thread                     */
/* ------------------------------------------------------------------ */
__global__ void sgemm_kernel(const float* __restrict__ Bw,
                             const float* __restrict__ bias)
{
    const int Kdim = 263;
    __shared__ float As[8][132];
    __shared__ float Bs[8][128];
    int tid = threadIdx.x;
    int brow = blockIdx.y * 128, bcol = blockIdx.x * 128;
    int tr = tid / 16, tc = tid % 16;

    float acc[8][8];
    #pragma unroll
    for (int x = 0; x < 8; x++)
        #pragma unroll
        for (int y = 0; y < 8; y++) acc[x][y] = 0.f;

    for (int k0 = 0; k0 < Kdim; k0 += 8){
        #pragma unroll
        for (int l = 0; l < 4; l++){
            int idx = tid + l*256;
            int kk = idx & 7, r = idx >> 3;
            int gk = k0 + kk;
            As[kk][r] = (gk < Kdim) ? g_sin[(size_t)(brow + r)*SIN_LD + gk] : 0.f;
        }
        #pragma unroll
        for (int l = 0; l < 4; l++){
            int idx = tid + l*256;
            int cc = idx & 127, kk = idx >> 7;
            int gk = k0 + kk;
            Bs[kk][cc] = (gk < Kdim) ? Bw[(size_t)gk*1024 + bcol + cc] : 0.f;
        }
        __syncthreads();
        #pragma unroll
        for (int kk = 0; kk < 8; kk++){
            float a[8], bb[8];
            #pragma unroll
            for (int x = 0; x < 8; x++){ a[x]  = As[kk][tr*8 + x]; }
            #pragma unroll
            for (int y = 0; y < 8; y++){ bb[y] = Bs[kk][tc*8 + y]; }
            #pragma unroll
            for (int x = 0; x < 8; x++)
                #pragma unroll
                for (int y = 0; y < 8; y++)
                    acc[x][y] += a[x] * bb[y];
        }
        __syncthreads();
    }
    #pragma unroll
    for (int x = 0; x < 8; x++){
        int gr = brow + tr*8 + x;
        #pragma unroll
        for (int y = 0; y < 8; y++){
            int gc = bcol + tc*8 + y;
            g_spre[(size_t)gr*1024 + gc] = acc[x][y] + bias[gc];
        }
    }
}

/* ------------------------------------------------------------------ */
/* kernel 3: scalar layernorm + confidence RBF projection              */
/* ------------------------------------------------------------------ */
__global__ void ln_conf_kernel(const float* __restrict__ conf,
                               const float* __restrict__ gam,
                               const float* __restrict__ bet,
                               const float* __restrict__ cw,
                               const float* __restrict__ cb,
                               float* __restrict__ ns)
{
    int nid = blockIdx.x, tid = threadIdx.x;
    __shared__ float red[8];
    __shared__ float sh_mu, sh_rstd;
    __shared__ float rbf[16];

    if (tid < 16){
        float c = conf[nid];
        float z = (c - (float)tid / 15.f) / 0.0625f;
        rbf[tid] = expf(-z*z);
    }

    const float* rp = g_spre + (size_t)nid*1024;
    float v[4];
    float lsum = 0.f;
    #pragma unroll
    for (int l = 0; l < 4; l++){ v[l] = rp[tid + l*256]; lsum += v[l]; }
    #pragma unroll
    for (int o = 16; o; o >>= 1) lsum += __shfl_down_sync(0xffffffffu, lsum, o);
    if ((tid & 31) == 0) red[tid >> 5] = lsum;
    __syncthreads();
    if (tid == 0){
        float s = 0.f;
        #pragma unroll
        for (int w = 0; w < 8; w++) s += red[w];
        sh_mu = s * (1.f/1024.f);
    }
    __syncthreads();
    float mu = sh_mu;
    float ls2 = 0.f;
    #pragma unroll
    for (int l = 0; l < 4; l++){ float d = v[l] - mu; ls2 += d*d; }
    #pragma unroll
    for (int o = 16; o; o >>= 1) ls2 += __shfl_down_sync(0xffffffffu, ls2, o);
    if ((tid & 31) == 0) red[tid >> 5] = ls2;
    __syncthreads();
    if (tid == 0){
        float s = 0.f;
        #pragma unroll
        for (int w = 0; w < 8; w++) s += red[w];
        sh_rstd = 1.f / sqrtf(s * (1.f/1024.f) + 1e-4f);
    }
    __syncthreads();
    float rstd = sh_rstd;
    #pragma unroll
    for (int l = 0; l < 4; l++){
        int j = tid + l*256;
        float add = 0.f;
        #pragma unroll
        for (int t = 0; t < 16; t++) add += rbf[t] * cw[t*1024 + j];
        ns[(size_t)nid*1024 + j] = (v[l] - mu) * rstd * gam[j] + bet[j] + add + cb[j];
    }
}

/* ------------------------------------------------------------------ */
/* kernel 4: edges — top-30 selection + edge features + GVP + LN       */
/* one block (256 threads) per (b, i) row                              */
/* ------------------------------------------------------------------ */
__global__ void edge_kernel(const float* __restrict__ coords,
                            const int* __restrict__ res_idx,
                            const float* __restrict__ ews,   /* (35,32) */
                            const float* __restrict__ ewb,   /* (32)    */
                            const float* __restrict__ eg,
                            const float* __restrict__ eb,
                            const float* __restrict__ ewh,   /* (1,1) */
                            const float* __restrict__ ewv,   /* (1,1) */
                            float* __restrict__ es_out,
                            float* __restrict__ ev_out,
                            float* __restrict__ ei_out)
{
    __shared__ unsigned long long skeys[L_];
    __shared__ unsigned long long warpmin[8];
    __shared__ int   selj[KNN];
    __shared__ float sfeat[KNN][36];
    __shared__ float espre[KNN][33];
    __shared__ float sevec[KNN][4];
    __shared__ float sW[35*32];

    int nid = blockIdx.x;
    int b = nid / L_, i = nid % L_;
    int tid = threadIdx.x;
    const float* Cb = coords + (size_t)b * L_ * 9;

    float xi = Cb[i*9 + 3], yi = Cb[i*9 + 4], zi = Cb[i*9 + 5];
    bool mi = g_mask[nid] != 0;

    for (int f = tid; f < 35*32; f += 256) sW[f] = ews[f];

    /* phase 1: keys = (f32_bits(D_adjust) << 32) | j  — D_adjust >= 0
       distance computed with explicit non-FMA ops to bit-match XLA:
       sqrt(((dx*dx + dy*dy) + dz*dz) + 1e-8)                          */
    for (int j = tid; j < L_; j += 256){
        bool mj = g_mask[b*L_ + j] != 0;
        int sd = abs(i - j);
        float val;
        if (mi && mj){
            if (sd <= 3) val = 0.f;
            else {
                float dx = __fadd_rn(xi, -Cb[j*9+3]);
                float dy = __fadd_rn(yi, -Cb[j*9+4]);
                float dz = __fadd_rn(zi, -Cb[j*9+5]);
                float s2 = __fadd_rn(__fadd_rn(__fadd_rn(__fmul_rn(dx,dx),
                                                          __fmul_rn(dy,dy)),
                                                __fmul_rn(dz,dz)), 1e-8f);
                val = sqrtf(s2);
            }
        } else {
            val = __fadd_rn(1e8f, __fmul_rn((float)sd, 1e6f));
        }
        skeys[j] = ((unsigned long long)__float_as_uint(val) << 32) | (unsigned)j;
    }
    __syncthreads();

    /* phase 2: 30 successive argmins (value asc, index asc tie-break) */
    for (int it = 0; it < KNN; it++){
        unsigned long long m = 0xFFFFFFFFFFFFFFFFULL;
        for (int j = tid; j < L_; j += 256) m = umin64(m, skeys[j]);
        #pragma unroll
        for (int o = 16; o; o >>= 1)
            m = umin64(m, __shfl_down_sync(0xffffffffu, m, o));
        if ((tid & 31) == 0) warpmin[tid >> 5] = m;
        __syncthreads();
        if (tid == 0){
            unsigned long long best = warpmin[0];
            #pragma unroll
            for (int w = 1; w < 8; w++) best = umin64(best, warpmin[w]);
            int j = (int)(best & 0xFFFFFFFFu);
            selj[it] = j;
            skeys[j] = 0xFFFFFFFFFFFFFFFFULL;
        }
        __syncthreads();
    }

    /* phase 3: scalar features for each selected edge */
    if (tid < KNN){
        int e = tid, j = selj[e];
        bool mj = g_mask[b*L_ + j] != 0;
        float xj = Cb[j*9+3], yj = Cb[j*9+4], zj = Cb[j*9+5];
        float dx = xi - xj, dy = yi - yj, dz = zi - zj;
        float dist = 0.f;
        if (mi && mj) dist = sqrtf(dx*dx + dy*dy + dz*dz + 1e-8f);
        #pragma unroll
        for (int t = 0; t < 16; t++){
            float c = (float)t * (20.f/15.f);
            float z = (dist - c) / 1.25f;
            sfeat[e][t] = expf(-z*z);
        }
        int dsi = res_idx[nid] - res_idx[b*L_ + j];
        float d = (float)max(-32, min(32, dsi));
        #pragma unroll
        for (int m8 = 0; m8 < 8; m8++){
            float fr = expf((float)(2*m8) * -0.5756462732485114f);
            float sv, cv; sincosf(d * fr, &sv, &cv);
            sfeat[e][16 + m8] = cv;
            sfeat[e][24 + m8] = sv;
        }
        sfeat[e][32] = mi ? 0.f : 1.f;
        sfeat[e][33] = mj ? 0.f : 1.f;
        float nrm = sqrtf(dx*dx + dy*dy + dz*dz + 1e-8f);
        float evx = dx/nrm, evy = dy/nrm, evz = dz/nrm;
        sevec[e][0] = evx; sevec[e][1] = evy; sevec[e][2] = evz;
        float whs = ewh[0];
        float vhx = evx*whs, vhy = evy*whs, vhz = evz*whs;
        sfeat[e][34] = sqrtf(fmaxf(vhx*vhx + vhy*vhy + vhz*vhz, 1e-8f));
    }
    __syncthreads();

    /* phase 4: es_pre = sfeat @ W + b  (30x35 @ 35x32) */
    for (int idx = tid; idx < KNN*32; idx += 256){
        int e = idx >> 5, o = idx & 31;
        float s = ewb[o];
        #pragma unroll
        for (int f = 0; f < 35; f++) s += sfeat[e][f] * sW[f*32 + o];
        espre[e][o] = s;
    }
    __syncthreads();

    /* phase 5: layernorm + vector output + edge index */
    if (tid < KNN){
        int e = tid;
        float mu = 0.f;
        #pragma unroll
        for (int o = 0; o < 32; o++) mu += espre[e][o];
        mu *= (1.f/32.f);
        float var = 0.f;
        #pragma unroll
        for (int o = 0; o < 32; o++){ float dd = espre[e][o] - mu; var += dd*dd; }
        var *= (1.f/32.f);
        float rstd = 1.f / sqrtf(var + 1e-4f);
        size_t gid = (size_t)nid * KNN + e;
        float* eo = es_out + gid*32;
        #pragma unroll
        for (int o = 0; o < 32; o++)
            eo[o] = (espre[e][o] - mu) * rstd * eg[o] + eb[o];

        float ww = ewh[0] * ewv[0];
        float vx = sevec[e][0]*ww, vy = sevec[e][1]*ww, vz = sevec[e][2]*ww;
        float dn = sqrtf(fmaxf(vx*vx + vy*vy + vz*vz, 1e-8f));
        float* vo = ev_out + gid*3;
        vo[0] = vx/dn; vo[1] = vy/dn; vo[2] = vz/dn;

        ei_out[gid]                 = (float)nid;                 /* src */
        ei_out[(size_t)NEDGE + gid] = (float)(b*L_ + selj[e]);    /* dst */
    }
}

/* ------------------------------------------------------------------ */
extern "C" void kernel_launch(void* const* d_in, const int* in_sizes, int n_in,
                              void* d_out, int out_size)
{
    const float*         coords     = (const float*)d_in[0];
    const unsigned char* cmask_raw  = (const unsigned char*)d_in[1];
    const int*           res_idx    = (const int*)d_in[2];
    /* d_in[3] = padding_mask (all false, unused) */
    const float*         confidence = (const float*)d_in[4];
    const float*         node_wh    = (const float*)d_in[5];
    const float*         node_ws_w  = (const float*)d_in[6];
    const float*         node_ws_b  = (const float*)d_in[7];
    const float*         node_wv    = (const float*)d_in[8];
    const float*         node_ln_g  = (const float*)d_in[9];
    const float*         node_ln_b  = (const float*)d_in[10];
    const float*         edge_wh    = (const float*)d_in[11];
    const float*         edge_ws_w  = (const float*)d_in[12];
    const float*         edge_ws_b  = (const float*)d_in[13];
    const float*         edge_wv    = (const float*)d_in[14];
    const float*         edge_ln_g  = (const float*)d_in[15];
    const float*         edge_ln_b  = (const float*)d_in[16];
    const float*         conf_w     = (const float*)d_in[17];
    const float*         conf_b     = (const float*)d_in[18];

    float* out = (float*)d_out;
    float* ns = out;                                  /* 8192*1024        */
    float* nv = ns + (size_t)NNODE*1024;              /* 8192*256*3       */
    float* es = nv + (size_t)NNODE*256*3;             /* 245760*32        */
    float* ev = es + (size_t)NEDGE*32;                /* 245760*3         */
    float* ei = ev + (size_t)NEDGE*3;                 /* 2*245760         */

    mask_prep_kernel<<<1, 1024>>>(cmask_raw);
    prep_M_kernel<<<1, 256>>>(node_wh, node_wv);
    node_feat_kernel<<<NNODE, 256>>>(coords, node_wh, nv);
    sgemm_kernel<<<dim3(8, 64), 256>>>(node_ws_w, node_ws_b);
    ln_conf_kernel<<<NNODE, 256>>>(confidence, node_ln_g, node_ln_b, conf_w, conf_b, ns);
    edge_kernel<<<NNODE, 256>>>(coords, res_idx,
                                edge_ws_w, edge_ws_b, edge_ln_g, edge_ln_b,
                                edge_wh, edge_wv, es, ev, ei);
    (void)in_sizes; (void)n_in; (void)out_size;
}

// round 3
// speedup vs baseline: 1.2892x; 1.2892x over previous
#include <cuda_runtime.h>
#include <math.h>

#define B_    4
#define L_    2048
#define KNN   30
#define NNODE (B_*L_)          /* 8192   */
#define NEDGE (NNODE*KNN)      /* 245760 */
#define SIN_LD 264             /* padded row stride for s_in (263 features) */

/* ------------------------------------------------------------------ */
/* static device scratch                                               */
/* ------------------------------------------------------------------ */
__device__ float g_M[768];                          /* wh @ wv  (3 x 256) */
__device__ float g_sin[(size_t)NNODE * SIN_LD];     /* GVP scalar input   */
__device__ float g_spre[(size_t)NNODE * 1024];      /* pre-LN scalar out  */
__device__ unsigned char g_mask[NNODE];             /* expanded coord_mask */
__device__ float4 g_ca[NNODE];                      /* CA xyz + mask flag  */
__device__ float g_geom[(size_t)NNODE * 16];        /* per-node geometry   */

struct F3 { float x, y, z; };
__device__ __forceinline__ F3 mkf3(float x, float y, float z){ F3 r; r.x=x; r.y=y; r.z=z; return r; }
__device__ __forceinline__ F3 sub3(F3 a, F3 b){ return mkf3(a.x-b.x, a.y-b.y, a.z-b.z); }
__device__ __forceinline__ F3 add3(F3 a, F3 b){ return mkf3(a.x+b.x, a.y+b.y, a.z+b.z); }
__device__ __forceinline__ float dot3(F3 a, F3 b){ return a.x*b.x + a.y*b.y + a.z*b.z; }
__device__ __forceinline__ F3 cross3(F3 a, F3 b){
    return mkf3(a.y*b.z - a.z*b.y, a.z*b.x - a.x*b.z, a.x*b.y - a.y*b.x);
}
__device__ __forceinline__ F3 norml(F3 a){
    float n = sqrtf(dot3(a,a) + 1e-8f);
    return mkf3(a.x/n, a.y/n, a.z/n);
}
__device__ __forceinline__ unsigned long long umin64(unsigned long long a, unsigned long long b){
    return a < b ? a : b;
}

/* ------------------------------------------------------------------ */
/* kernel -1: detect bool storage layout and expand coord_mask         */
/* ------------------------------------------------------------------ */
__global__ void mask_prep_kernel(const unsigned char* __restrict__ mraw){
    __shared__ int sA, sB;
    int tid = threadIdx.x;
    if (tid == 0){ sA = 0; sB = 0; }
    __syncthreads();
    int la = 0, lb = 0;
    for (int i = tid; i < 8192; i += 1024){
        unsigned char v = mraw[i];
        if (v){
            if (i & 3) la++;
            else if ((i & 7) == 4) lb++;
        }
    }
    if (la) atomicAdd(&sA, la);
    if (lb) atomicAdd(&sB, lb);
    __syncthreads();
    int mode = (sA > 0) ? 0 : ((sB > 0) ? 1 : 2);   /* 0=byte 1=i32 2=i64 */
    for (int i = tid; i < NNODE; i += 1024){
        unsigned char v;
        if (mode == 0)      v = mraw[i] ? 1 : 0;
        else if (mode == 1) v = ((const int*)mraw)[i] ? 1 : 0;
        else                v = ((const long long*)mraw)[i] ? 1 : 0;
        g_mask[i] = v;
    }
}

/* pack CA coords + mask flag into float4 */
__global__ void ca_pack_kernel(const float* __restrict__ coords){
    int nid = blockIdx.x * 256 + threadIdx.x;
    if (nid >= NNODE) return;
    const float* p = coords + (size_t)nid*9 + 3;
    float4 v; v.x = p[0]; v.y = p[1]; v.z = p[2];
    v.w = g_mask[nid] ? 1.f : 0.f;
    g_ca[nid] = v;
}

/* ------------------------------------------------------------------ */
/* kernel 0: M = wh @ wv   (3x256 @ 256x256)                            */
/* ------------------------------------------------------------------ */
__global__ void prep_M_kernel(const float* __restrict__ wh, const float* __restrict__ wv){
    int v = threadIdx.x;
    #pragma unroll
    for (int i = 0; i < 3; i++){
        float s = 0.f;
        for (int h = 0; h < 256; h++) s += wh[i*256 + h] * wv[h*256 + v];
        g_M[i*256 + v] = s;
    }
}

/* ------------------------------------------------------------------ */
/* kernel 1a: per-node geometry (one thread per node)                  */
/* ------------------------------------------------------------------ */
__device__ __forceinline__ F3 ldatom(const float* Cb, int r, int a){
    const float* p = Cb + ((size_t)r*3 + a)*3;
    return mkf3(p[0], p[1], p[2]);
}

__global__ void geom_kernel(const float* __restrict__ coords){
    int nid = blockIdx.x * 256 + threadIdx.x;
    if (nid >= NNODE) return;
    int b = nid / L_, i = nid % L_;
    const float* Cb = coords + (size_t)b * L_ * 9;
    float* G = g_geom + (size_t)nid * 16;

    F3 xca = ldatom(Cb, i, 1);
    F3 fwd = mkf3(0.f,0.f,0.f), bk = mkf3(0.f,0.f,0.f);
    if (i < L_-1) fwd = norml(sub3(ldatom(Cb, i+1, 1), xca));
    if (i > 0)    bk  = norml(sub3(ldatom(Cb, i-1, 1), xca));
    F3 nn = norml(sub3(ldatom(Cb, i, 0), xca));
    F3 cc = norml(sub3(ldatom(Cb, i, 2), xca));
    F3 bis  = norml(add3(cc, nn));
    F3 perp = norml(cross3(cc, nn));
    const float k1 = 0.5773502691896258f;
    const float k2 = 0.8164965809277260f;
    F3 sc = mkf3(-bis.x*k1 - perp.x*k2, -bis.y*k1 - perp.y*k2, -bis.z*k1 - perp.z*k2);
    G[0]=fwd.x; G[1]=fwd.y; G[2]=fwd.z;
    G[3]=bk.x;  G[4]=bk.y;  G[5]=bk.z;
    G[6]=sc.x;  G[7]=sc.y;  G[8]=sc.z;

    F3 U[5];
    #pragma unroll
    for (int a = 0; a < 5; a++){
        int t = 3*i - 1 + a;
        if (t >= 0 && t <= 3*L_ - 2){
            F3 p0 = ldatom(Cb, t/3, t%3);
            int t1 = t + 1;
            F3 p1 = ldatom(Cb, t1/3, t1%3);
            U[a] = norml(sub3(p1, p0));
        } else U[a] = mkf3(0.f,0.f,0.f);
    }
    #pragma unroll
    for (int a = 0; a < 3; a++){
        int t = 3*i - 1 + a;
        float D = 0.f;
        if (t >= 0 && t <= 3*L_ - 4){
            F3 u2 = U[a], u1 = U[a+1], u0 = U[a+2];
            F3 n2 = norml(cross3(u2, u1));
            F3 n1 = norml(cross3(u1, u0));
            float cd = dot3(n2, n1);
            cd = fminf(fmaxf(cd, -1.f + 1e-7f), 1.f - 1e-7f);
            float sg = dot3(u2, n1);
            float s = (sg > 0.f) ? 1.f : ((sg < 0.f) ? -1.f : 0.f);
            D = s * acosf(cd);
        }
        G[9+a]  = cosf(D);
        G[12+a] = sinf(D);
    }
    G[15] = g_mask[nid] ? 1.f : 0.f;
}

/* ------------------------------------------------------------------ */
/* kernel 1b: GVP vector path + vector layernorm (block per node)      */
/* ------------------------------------------------------------------ */
__global__ void node_main_kernel(const float* __restrict__ wh,
                                 float* __restrict__ nv_out)
{
    int nid = blockIdx.x;
    int tid = threadIdx.x;
    __shared__ float G[16];
    __shared__ float sh_red[8];
    __shared__ float sh_denom;

    if (tid < 16) G[tid] = g_geom[(size_t)nid*16 + tid];
    __syncthreads();

    F3 v0 = mkf3(G[0], G[1], G[2]);
    F3 v1 = mkf3(G[3], G[4], G[5]);
    F3 v2 = mkf3(G[6], G[7], G[8]);

    int h = tid;
    float w0 = wh[h], w1 = wh[256+h], w2 = wh[512+h];
    F3 vh = mkf3(v0.x*w0 + v1.x*w1 + v2.x*w2,
                 v0.y*w0 + v1.y*w1 + v2.y*w2,
                 v0.z*w0 + v1.z*w1 + v2.z*w2);
    float vn = sqrtf(fmaxf(dot3(vh,vh), 1e-8f));
    g_sin[(size_t)nid*SIN_LD + 7 + h] = vn;
    if (tid < 7) g_sin[(size_t)nid*SIN_LD + tid] = G[9 + tid];

    float m0 = g_M[h], m1 = g_M[256+h], m2 = g_M[512+h];
    F3 vo = mkf3(v0.x*m0 + v1.x*m1 + v2.x*m2,
                 v0.y*m0 + v1.y*m1 + v2.y*m2,
                 v0.z*m0 + v1.z*m1 + v2.z*m2);
    float c = fmaxf(dot3(vo,vo), 1e-8f);
    #pragma unroll
    for (int o = 16; o; o >>= 1) c += __shfl_down_sync(0xffffffffu, c, o);
    if ((tid & 31) == 0) sh_red[tid >> 5] = c;
    __syncthreads();
    if (tid == 0){
        float s = 0.f;
        #pragma unroll
        for (int w = 0; w < 8; w++) s += sh_red[w];
        sh_denom = sqrtf(s * (1.f/256.f));
    }
    __syncthreads();
    float dn = sh_denom;
    float* o = nv_out + (size_t)nid*768 + (size_t)h*3;
    o[0] = vo.x/dn; o[1] = vo.y/dn; o[2] = vo.z/dn;
}

/* ------------------------------------------------------------------ */
/* kernel 2: SGEMM  C[8192,1024] = A[8192,263] @ B[263,1024] + bias    */
/* 128x128 tile, BK=8, 256 threads, 8x8/thread, double-buffered        */
/* ------------------------------------------------------------------ */
__global__ void __launch_bounds__(256) sgemm_kernel(const float* __restrict__ Bw,
                                                    const float* __restrict__ bias)
{
    const int Kdim = 263;
    const int NT = 33;                     /* ceil(263/8) */
    __shared__ float As[2][8][132];
    __shared__ float Bs[2][8][128];
    int tid = threadIdx.x;
    int brow = blockIdx.y * 128, bcol = blockIdx.x * 128;
    int tr = tid / 16, tc = tid % 16;

    /* A loader mapping: r = tid>>1 (0..127), kq = tid&1 (float4 at k0+kq*4) */
    int ar = tid >> 1, akq = tid & 1;
    /* B loader mapping: kk = tid>>5 (0..7), cc4 = (tid&31)*4 */
    int bkk = tid >> 5, bcc = (tid & 31) * 4;

    float acc[8][8];
    #pragma unroll
    for (int x = 0; x < 8; x++)
        #pragma unroll
        for (int y = 0; y < 8; y++) acc[x][y] = 0.f;

    /* load tile 0 */
    {
        const float4* pa = (const float4*)(g_sin + (size_t)(brow + ar)*SIN_LD + akq*4);
        float4 va = *pa;
        As[0][akq*4+0][ar] = va.x; As[0][akq*4+1][ar] = va.y;
        As[0][akq*4+2][ar] = va.z; As[0][akq*4+3][ar] = va.w;
        float4 vb = make_float4(0.f,0.f,0.f,0.f);
        if (bkk < Kdim) vb = *(const float4*)(Bw + (size_t)bkk*1024 + bcol + bcc);
        *(float4*)&Bs[0][bkk][bcc] = vb;
    }
    __syncthreads();

    for (int t = 0; t < NT; t++){
        int cur = t & 1;
        float4 va, vb;
        bool more = (t + 1 < NT);
        if (more){
            int k0 = (t+1) * 8;
            va = *(const float4*)(g_sin + (size_t)(brow + ar)*SIN_LD + k0 + akq*4);
            int gk = k0 + bkk;
            vb = make_float4(0.f,0.f,0.f,0.f);
            if (gk < Kdim) vb = *(const float4*)(Bw + (size_t)gk*1024 + bcol + bcc);
        }
        #pragma unroll
        for (int kk = 0; kk < 8; kk++){
            float a[8], bb[8];
            #pragma unroll
            for (int x = 0; x < 8; x++) a[x]  = As[cur][kk][tr*8 + x];
            #pragma unroll
            for (int y = 0; y < 8; y++) bb[y] = Bs[cur][kk][tc*8 + y];
            #pragma unroll
            for (int x = 0; x < 8; x++)
                #pragma unroll
                for (int y = 0; y < 8; y++)
                    acc[x][y] += a[x] * bb[y];
        }
        if (more){
            int nxt = 1 - cur;
            As[nxt][akq*4+0][ar] = va.x; As[nxt][akq*4+1][ar] = va.y;
            As[nxt][akq*4+2][ar] = va.z; As[nxt][akq*4+3][ar] = va.w;
            *(float4*)&Bs[nxt][bkk][bcc] = vb;
        }
        __syncthreads();
    }

    #pragma unroll
    for (int x = 0; x < 8; x++){
        int gr = brow + tr*8 + x;
        #pragma unroll
        for (int y4 = 0; y4 < 2; y4++){
            int gc = bcol + tc*8 + y4*4;
            float4 v;
            v.x = acc[x][y4*4+0] + bias[gc+0];
            v.y = acc[x][y4*4+1] + bias[gc+1];
            v.z = acc[x][y4*4+2] + bias[gc+2];
            v.w = acc[x][y4*4+3] + bias[gc+3];
            *(float4*)(g_spre + (size_t)gr*1024 + gc) = v;
        }
    }
}

/* ------------------------------------------------------------------ */
/* kernel 3: scalar layernorm + confidence RBF projection              */
/* ------------------------------------------------------------------ */
__global__ void ln_conf_kernel(const float* __restrict__ conf,
                               const float* __restrict__ gam,
                               const float* __restrict__ bet,
                               const float* __restrict__ cw,
                               const float* __restrict__ cb,
                               float* __restrict__ ns)
{
    int nid = blockIdx.x, tid = threadIdx.x;
    __shared__ float red[8];
    __shared__ float sh_mu, sh_rstd;
    __shared__ float rbf[16];

    if (tid < 16){
        float c = conf[nid];
        float z = (c - (float)tid / 15.f) / 0.0625f;
        rbf[tid] = expf(-z*z);
    }

    const float* rp = g_spre + (size_t)nid*1024;
    float v[4];
    float lsum = 0.f;
    #pragma unroll
    for (int l = 0; l < 4; l++){ v[l] = rp[tid + l*256]; lsum += v[l]; }
    #pragma unroll
    for (int o = 16; o; o >>= 1) lsum += __shfl_down_sync(0xffffffffu, lsum, o);
    if ((tid & 31) == 0) red[tid >> 5] = lsum;
    __syncthreads();
    if (tid == 0){
        float s = 0.f;
        #pragma unroll
        for (int w = 0; w < 8; w++) s += red[w];
        sh_mu = s * (1.f/1024.f);
    }
    __syncthreads();
    float mu = sh_mu;
    float ls2 = 0.f;
    #pragma unroll
    for (int l = 0; l < 4; l++){ float d = v[l] - mu; ls2 += d*d; }
    #pragma unroll
    for (int o = 16; o; o >>= 1) ls2 += __shfl_down_sync(0xffffffffu, ls2, o);
    if ((tid & 31) == 0) red[tid >> 5] = ls2;
    __syncthreads();
    if (tid == 0){
        float s = 0.f;
        #pragma unroll
        for (int w = 0; w < 8; w++) s += red[w];
        sh_rstd = 1.f / sqrtf(s * (1.f/1024.f) + 1e-4f);
    }
    __syncthreads();
    float rstd = sh_rstd;
    #pragma unroll
    for (int l = 0; l < 4; l++){
        int j = tid + l*256;
        float add = 0.f;
        #pragma unroll
        for (int t = 0; t < 16; t++) add += rbf[t] * cw[t*1024 + j];
        ns[(size_t)nid*1024 + j] = (v[l] - mu) * rstd * gam[j] + bet[j] + add + cb[j];
    }
}

/* ------------------------------------------------------------------ */
/* kernel 4: edges — register-resident top-30 + features + GVP + LN    */
/* one block (256 threads) per (b, i) row; 8 candidates per thread     */
/* ------------------------------------------------------------------ */
#define CSWAP(a,b) { if (k[a] > k[b]) { unsigned long long t_ = k[a]; k[a] = k[b]; k[b] = t_; } }

__global__ void __launch_bounds__(256) edge_kernel(
                            const int* __restrict__ res_idx,
                            const float* __restrict__ ews,   /* (35,32) */
                            const float* __restrict__ ewb,   /* (32)    */
                            const float* __restrict__ eg,
                            const float* __restrict__ eb,
                            const float* __restrict__ ewh,   /* (1,1) */
                            const float* __restrict__ ewv,   /* (1,1) */
                            float* __restrict__ es_out,
                            float* __restrict__ ev_out,
                            float* __restrict__ ei_out)
{
    __shared__ unsigned long long warpmin[8];
    __shared__ unsigned long long sbest[KNN];
    __shared__ float sfeat[KNN][36];
    __shared__ float espre[KNN][33];
    __shared__ float sevec[KNN][4];
    __shared__ float sW[35*32];

    int nid = blockIdx.x;
    int b = nid / L_, i = nid % L_;
    int tid = threadIdx.x;

    float4 ci = g_ca[nid];
    float xi = ci.x, yi = ci.y, zi = ci.z;
    bool mi = ci.w != 0.f;

    for (int f = tid; f < 35*32; f += 256) sW[f] = ews[f];

    /* build 8 keys per thread: key = (f32_bits(D_adjust) << 32) | j
       (same non-FMA arithmetic as the passing R2 kernel)              */
    unsigned long long k[8];
    #pragma unroll
    for (int u = 0; u < 8; u++){
        int j = tid + u*256;
        float4 cj = g_ca[b*L_ + j];
        bool mj = cj.w != 0.f;
        int sd = abs(i - j);
        float val;
        if (mi && mj){
            if (sd <= 3) val = 0.f;
            else {
                float dx = __fadd_rn(xi, -cj.x);
                float dy = __fadd_rn(yi, -cj.y);
                float dz = __fadd_rn(zi, -cj.z);
                float s2 = __fadd_rn(__fadd_rn(__fadd_rn(__fmul_rn(dx,dx),
                                                          __fmul_rn(dy,dy)),
                                                __fmul_rn(dz,dz)), 1e-8f);
                val = sqrtf(s2);
            }
        } else {
            val = __fadd_rn(1e8f, __fmul_rn((float)sd, 1e6f));
        }
        k[u] = ((unsigned long long)__float_as_uint(val) << 32) | (unsigned)j;
    }
    /* sort 8 ascending (Batcher, 19 comparators) */
    CSWAP(0,1) CSWAP(2,3) CSWAP(4,5) CSWAP(6,7)
    CSWAP(0,2) CSWAP(1,3) CSWAP(4,6) CSWAP(5,7)
    CSWAP(1,2) CSWAP(5,6) CSWAP(0,4) CSWAP(3,7)
    CSWAP(1,5) CSWAP(2,6)
    CSWAP(1,4) CSWAP(3,6)
    CSWAP(2,4) CSWAP(3,5)
    CSWAP(3,4)

    /* 30 successive block argmins over per-thread heads */
    int p = 0;
    for (int it = 0; it < KNN; it++){
        unsigned long long h = (p < 8) ? k[p] : 0xFFFFFFFFFFFFFFFFULL;
        unsigned long long m = h;
        #pragma unroll
        for (int o = 16; o; o >>= 1)
            m = umin64(m, __shfl_down_sync(0xffffffffu, m, o));
        if ((tid & 31) == 0) warpmin[tid >> 5] = m;
        __syncthreads();
        if (tid == 0){
            unsigned long long best = warpmin[0];
            #pragma unroll
            for (int w = 1; w < 8; w++) best = umin64(best, warpmin[w]);
            sbest[it] = best;
        }
        __syncthreads();
        if (h == sbest[it]) p++;   /* keys unique -> exactly one winner */
    }

    /* phase 3: scalar features for each selected edge */
    if (tid < KNN){
        int e = tid, j = (int)(sbest[e] & 0xFFFFFFFFu);
        float4 cj = g_ca[b*L_ + j];
        bool mj = cj.w != 0.f;
        float dx = xi - cj.x, dy = yi - cj.y, dz = zi - cj.z;
        float dist = 0.f;
        if (mi && mj) dist = sqrtf(dx*dx + dy*dy + dz*dz + 1e-8f);
        #pragma unroll
        for (int t = 0; t < 16; t++){
            float c = (float)t * (20.f/15.f);
            float z = (dist - c) / 1.25f;
            sfeat[e][t] = expf(-z*z);
        }
        int dsi = res_idx[nid] - res_idx[b*L_ + j];
        float d = (float)max(-32, min(32, dsi));
        #pragma unroll
        for (int m8 = 0; m8 < 8; m8++){
            float fr = expf((float)(2*m8) * -0.5756462732485114f);
            float sv, cv; sincosf(d * fr, &sv, &cv);
            sfeat[e][16 + m8] = cv;
            sfeat[e][24 + m8] = sv;
        }
        sfeat[e][32] = mi ? 0.f : 1.f;
        sfeat[e][33] = mj ? 0.f : 1.f;
        float nrm = sqrtf(dx*dx + dy*dy + dz*dz + 1e-8f);
        float evx = dx/nrm, evy = dy/nrm, evz = dz/nrm;
        sevec[e][0] = evx; sevec[e][1] = evy; sevec[e][2] = evz;
        sevec[e][3] = (float)j;
        float whs = ewh[0];
        float vhx = evx*whs, vhy = evy*whs, vhz = evz*whs;
        sfeat[e][34] = sqrtf(fmaxf(vhx*vhx + vhy*vhy + vhz*vhz, 1e-8f));
    }
    __syncthreads();

    /* phase 4: es_pre = sfeat @ W + b  (30x35 @ 35x32) */
    for (int idx = tid; idx < KNN*32; idx += 256){
        int e = idx >> 5, o = idx & 31;
        float s = ewb[o];
        #pragma unroll
        for (int f = 0; f < 35; f++) s += sfeat[e][f] * sW[f*32 + o];
        espre[e][o] = s;
    }
    __syncthreads();

    /* phase 5: layernorm + vector output + edge index */
    if (tid < KNN){
        int e = tid;
        float mu = 0.f;
        #pragma unroll
        for (int o = 0; o < 32; o++) mu += espre[e][o];
        mu *= (1.f/32.f);
        float var = 0.f;
        #pragma unroll
        for (int o = 0; o < 32; o++){ float dd = espre[e][o] - mu; var += dd*dd; }
        var *= (1.f/32.f);
        float rstd = 1.f / sqrtf(var + 1e-4f);
        size_t gid = (size_t)nid * KNN + e;
        float* eo = es_out + gid*32;
        #pragma unroll
        for (int o = 0; o < 32; o++)
            eo[o] = (espre[e][o] - mu) * rstd * eg[o] + eb[o];

        float ww = ewh[0] * ewv[0];
        float vx = sevec[e][0]*ww, vy = sevec[e][1]*ww, vz = sevec[e][2]*ww;
        float dn = sqrtf(fmaxf(vx*vx + vy*vy + vz*vz, 1e-8f));
        float* vo = ev_out + gid*3;
        vo[0] = vx/dn; vo[1] = vy/dn; vo[2] = vz/dn;

        ei_out[gid]                 = (float)nid;
        ei_out[(size_t)NEDGE + gid] = (float)(b*L_ + (int)sevec[e][3]);
    }
}

/* ------------------------------------------------------------------ */
extern "C" void kernel_launch(void* const* d_in, const int* in_sizes, int n_in,
                              void* d_out, int out_size)
{
    const float*         coords     = (const float*)d_in[0];
    const unsigned char* cmask_raw  = (const unsigned char*)d_in[1];
    const int*           res_idx    = (const int*)d_in[2];
    const float*         confidence = (const float*)d_in[4];
    const float*         node_wh    = (const float*)d_in[5];
    const float*         node_ws_w  = (const float*)d_in[6];
    const float*         node_ws_b  = (const float*)d_in[7];
    const float*         node_wv    = (const float*)d_in[8];
    const float*         node_ln_g  = (const float*)d_in[9];
    const float*         node_ln_b  = (const float*)d_in[10];
    const float*         edge_wh    = (const float*)d_in[11];
    const float*         edge_ws_w  = (const float*)d_in[12];
    const float*         edge_ws_b  = (const float*)d_in[13];
    const float*         edge_wv    = (const float*)d_in[14];
    const float*         edge_ln_g  = (const float*)d_in[15];
    const float*         edge_ln_b  = (const float*)d_in[16];
    const float*         conf_w     = (const float*)d_in[17];
    const float*         conf_b     = (const float*)d_in[18];

    float* out = (float*)d_out;
    float* ns = out;
    float* nv = ns + (size_t)NNODE*1024;
    float* es = nv + (size_t)NNODE*256*3;
    float* ev = es + (size_t)NEDGE*32;
    float* ei = ev + (size_t)NEDGE*3;

    mask_prep_kernel<<<1, 1024>>>(cmask_raw);
    ca_pack_kernel<<<32, 256>>>(coords);
    prep_M_kernel<<<1, 256>>>(node_wh, node_wv);
    geom_kernel<<<32, 256>>>(coords);
    node_main_kernel<<<NNODE, 256>>>(node_wh, nv);
    sgemm_kernel<<<dim3(8, 64), 256>>>(node_ws_w, node_ws_b);
    ln_conf_kernel<<<NNODE, 256>>>(confidence, node_ln_g, node_ln_b, conf_w, conf_b, ns);
    edge_kernel<<<NNODE, 256>>>(res_idx,
                                edge_ws_w, edge_ws_b, edge_ln_g, edge_ln_b,
                                edge_wh, edge_wv, es, ev, ei);
    (void)in_sizes; (void)n_in; (void)out_size;
}

// round 4
// speedup vs baseline: 1.7905x; 1.3888x over previous
#include <cuda_runtime.h>
#include <math.h>

#define B_    4
#define L_    2048
#define KNN   30
#define NNODE (B_*L_)          /* 8192   */
#define NEDGE (NNODE*KNN)      /* 245760 */
#define SIN_LD 272             /* padded row stride for s_in (263 real + pad) */
#define KPAD  272

/* ------------------------------------------------------------------ */
/* static device scratch                                               */
/* ------------------------------------------------------------------ */
__device__ float g_M[768];                          /* wh @ wv  (3 x 256) */
__device__ float g_sin[(size_t)NNODE * SIN_LD];     /* GVP scalar input   */
__device__ float g_spre[(size_t)NNODE * 1024];      /* pre-LN scalar out  */
__device__ unsigned char g_mask[NNODE];             /* expanded coord_mask */
__device__ float4 g_ca[NNODE];                      /* CA xyz + mask flag  */
__device__ float g_geom[(size_t)NNODE * 16];        /* per-node geometry   */
__device__ float g_bpad[(size_t)KPAD * 1024];       /* padded B weights    */

struct F3 { float x, y, z; };
__device__ __forceinline__ F3 mkf3(float x, float y, float z){ F3 r; r.x=x; r.y=y; r.z=z; return r; }
__device__ __forceinline__ F3 sub3(F3 a, F3 b){ return mkf3(a.x-b.x, a.y-b.y, a.z-b.z); }
__device__ __forceinline__ F3 add3(F3 a, F3 b){ return mkf3(a.x+b.x, a.y+b.y, a.z+b.z); }
__device__ __forceinline__ float dot3(F3 a, F3 b){ return a.x*b.x + a.y*b.y + a.z*b.z; }
__device__ __forceinline__ F3 cross3(F3 a, F3 b){
    return mkf3(a.y*b.z - a.z*b.y, a.z*b.x - a.x*b.z, a.x*b.y - a.y*b.x);
}
__device__ __forceinline__ F3 norml(F3 a){
    float n = sqrtf(dot3(a,a) + 1e-8f);
    return mkf3(a.x/n, a.y/n, a.z/n);
}

/* ------------------------------------------------------------------ */
/* mask layout detect + expand                                         */
/* ------------------------------------------------------------------ */
__global__ void mask_prep_kernel(const unsigned char* __restrict__ mraw){
    __shared__ int sA, sB;
    int tid = threadIdx.x;
    if (tid == 0){ sA = 0; sB = 0; }
    __syncthreads();
    int la = 0, lb = 0;
    for (int i = tid; i < 8192; i += 1024){
        unsigned char v = mraw[i];
        if (v){
            if (i & 3) la++;
            else if ((i & 7) == 4) lb++;
        }
    }
    if (la) atomicAdd(&sA, la);
    if (lb) atomicAdd(&sB, lb);
    __syncthreads();
    int mode = (sA > 0) ? 0 : ((sB > 0) ? 1 : 2);
    for (int i = tid; i < NNODE; i += 1024){
        unsigned char v;
        if (mode == 0)      v = mraw[i] ? 1 : 0;
        else if (mode == 1) v = ((const int*)mraw)[i] ? 1 : 0;
        else                v = ((const long long*)mraw)[i] ? 1 : 0;
        g_mask[i] = v;
    }
}

__global__ void ca_pack_kernel(const float* __restrict__ coords){
    int nid = blockIdx.x * 256 + threadIdx.x;
    if (nid >= NNODE) return;
    const float* p = coords + (size_t)nid*9 + 3;
    float4 v; v.x = p[0]; v.y = p[1]; v.z = p[2];
    v.w = g_mask[nid] ? 1.f : 0.f;
    g_ca[nid] = v;
}

__global__ void prep_M_kernel(const float* __restrict__ wh, const float* __restrict__ wv){
    int v = threadIdx.x;
    #pragma unroll
    for (int i = 0; i < 3; i++){
        float s = 0.f;
        for (int h = 0; h < 256; h++) s += wh[i*256 + h] * wv[h*256 + v];
        g_M[i*256 + v] = s;
    }
}

__global__ void bpad_kernel(const float* __restrict__ Bw){
    int idx = blockIdx.x * 256 + threadIdx.x;
    if (idx >= KPAD*1024) return;
    int kk = idx >> 10, c = idx & 1023;
    g_bpad[idx] = (kk < 263) ? Bw[kk*1024 + c] : 0.f;
}

/* ------------------------------------------------------------------ */
/* per-node geometry (one thread per node)                             */
/* ------------------------------------------------------------------ */
__device__ __forceinline__ F3 ldatom(const float* Cb, int r, int a){
    const float* p = Cb + ((size_t)r*3 + a)*3;
    return mkf3(p[0], p[1], p[2]);
}

__global__ void geom_kernel(const float* __restrict__ coords){
    int nid = blockIdx.x * 256 + threadIdx.x;
    if (nid >= NNODE) return;
    int b = nid / L_, i = nid % L_;
    const float* Cb = coords + (size_t)b * L_ * 9;
    float* G = g_geom + (size_t)nid * 16;

    F3 xca = ldatom(Cb, i, 1);
    F3 fwd = mkf3(0.f,0.f,0.f), bk = mkf3(0.f,0.f,0.f);
    if (i < L_-1) fwd = norml(sub3(ldatom(Cb, i+1, 1), xca));
    if (i > 0)    bk  = norml(sub3(ldatom(Cb, i-1, 1), xca));
    F3 nn = norml(sub3(ldatom(Cb, i, 0), xca));
    F3 cc = norml(sub3(ldatom(Cb, i, 2), xca));
    F3 bis  = norml(add3(cc, nn));
    F3 perp = norml(cross3(cc, nn));
    const float k1 = 0.5773502691896258f;
    const float k2 = 0.8164965809277260f;
    F3 sc = mkf3(-bis.x*k1 - perp.x*k2, -bis.y*k1 - perp.y*k2, -bis.z*k1 - perp.z*k2);
    G[0]=fwd.x; G[1]=fwd.y; G[2]=fwd.z;
    G[3]=bk.x;  G[4]=bk.y;  G[5]=bk.z;
    G[6]=sc.x;  G[7]=sc.y;  G[8]=sc.z;

    F3 U[5];
    #pragma unroll
    for (int a = 0; a < 5; a++){
        int t = 3*i - 1 + a;
        if (t >= 0 && t <= 3*L_ - 2){
            F3 p0 = ldatom(Cb, t/3, t%3);
            int t1 = t + 1;
            F3 p1 = ldatom(Cb, t1/3, t1%3);
            U[a] = norml(sub3(p1, p0));
        } else U[a] = mkf3(0.f,0.f,0.f);
    }
    #pragma unroll
    for (int a = 0; a < 3; a++){
        int t = 3*i - 1 + a;
        float D = 0.f;
        if (t >= 0 && t <= 3*L_ - 4){
            F3 u2 = U[a], u1 = U[a+1], u0 = U[a+2];
            F3 n2 = norml(cross3(u2, u1));
            F3 n1 = norml(cross3(u1, u0));
            float cd = dot3(n2, n1);
            cd = fminf(fmaxf(cd, -1.f + 1e-7f), 1.f - 1e-7f);
            float sg = dot3(u2, n1);
            float s = (sg > 0.f) ? 1.f : ((sg < 0.f) ? -1.f : 0.f);
            D = s * acosf(cd);
        }
        G[9+a]  = cosf(D);
        G[12+a] = sinf(D);
    }
    G[15] = g_mask[nid] ? 1.f : 0.f;
}

/* ------------------------------------------------------------------ */
/* GVP vector path + vector layernorm (block per node)                 */
/* ------------------------------------------------------------------ */
__global__ void node_main_kernel(const float* __restrict__ wh,
                                 float* __restrict__ nv_out)
{
    int nid = blockIdx.x;
    int tid = threadIdx.x;
    __shared__ float G[16];
    __shared__ float sh_red[8];
    __shared__ float sh_denom;

    if (tid < 16) G[tid] = g_geom[(size_t)nid*16 + tid];
    if (tid < 9)  g_sin[(size_t)nid*SIN_LD + 263 + tid] = 0.f;   /* K pad */
    __syncthreads();

    F3 v0 = mkf3(G[0], G[1], G[2]);
    F3 v1 = mkf3(G[3], G[4], G[5]);
    F3 v2 = mkf3(G[6], G[7], G[8]);

    int h = tid;
    float w0 = wh[h], w1 = wh[256+h], w2 = wh[512+h];
    F3 vh = mkf3(v0.x*w0 + v1.x*w1 + v2.x*w2,
                 v0.y*w0 + v1.y*w1 + v2.y*w2,
                 v0.z*w0 + v1.z*w1 + v2.z*w2);
    float vn = sqrtf(fmaxf(dot3(vh,vh), 1e-8f));
    g_sin[(size_t)nid*SIN_LD + 7 + h] = vn;
    if (tid < 7) g_sin[(size_t)nid*SIN_LD + tid] = G[9 + tid];

    float m0 = g_M[h], m1 = g_M[256+h], m2 = g_M[512+h];
    F3 vo = mkf3(v0.x*m0 + v1.x*m1 + v2.x*m2,
                 v0.y*m0 + v1.y*m1 + v2.y*m2,
                 v0.z*m0 + v1.z*m1 + v2.z*m2);
    float c = fmaxf(dot3(vo,vo), 1e-8f);
    #pragma unroll
    for (int o = 16; o; o >>= 1) c += __shfl_down_sync(0xffffffffu, c, o);
    if ((tid & 31) == 0) sh_red[tid >> 5] = c;
    __syncthreads();
    if (tid == 0){
        float s = 0.f;
        #pragma unroll
        for (int w = 0; w < 8; w++) s += sh_red[w];
        sh_denom = sqrtf(s * (1.f/256.f));
    }
    __syncthreads();
    float dn = sh_denom;
    float* o = nv_out + (size_t)nid*768 + (size_t)h*3;
    o[0] = vo.x/dn; o[1] = vo.y/dn; o[2] = vo.z/dn;
}

/* ------------------------------------------------------------------ */
/* SGEMM  C[8192,1024] = A[8192,272p] @ Bpad[272,1024] + bias          */
/* 128x128 tile, BK=16, 256 threads, 8x8/thread, double-buffered       */
/* ------------------------------------------------------------------ */
__global__ void __launch_bounds__(256) sgemm_kernel(const float* __restrict__ bias)
{
    const int NT = KPAD / 16;             /* 17 */
    __shared__ float As[2][16][132];
    __shared__ float Bs[2][16][128];
    int tid = threadIdx.x;
    int brow = blockIdx.y * 128, bcol = blockIdx.x * 128;
    int tr = tid / 16, tc = tid % 16;

    float acc[8][8];
    #pragma unroll
    for (int x = 0; x < 8; x++)
        #pragma unroll
        for (int y = 0; y < 8; y++) acc[x][y] = 0.f;

    /* loader mappings: 512 float4 per operand per tile -> 2/thread */
    int aq0 = tid, aq1 = tid + 256;
    int ar0 = aq0 >> 2, ak0 = (aq0 & 3) * 4;
    int ar1 = aq1 >> 2, ak1 = (aq1 & 3) * 4;
    int bq0 = tid, bq1 = tid + 256;
    int bk0 = bq0 >> 5, bc0 = (bq0 & 31) * 4;
    int bk1 = bq1 >> 5, bc1 = (bq1 & 31) * 4;

    /* load tile 0 */
    {
        float4 a0 = *(const float4*)(g_sin + (size_t)(brow + ar0)*SIN_LD + ak0);
        float4 a1 = *(const float4*)(g_sin + (size_t)(brow + ar1)*SIN_LD + ak1);
        As[0][ak0+0][ar0]=a0.x; As[0][ak0+1][ar0]=a0.y; As[0][ak0+2][ar0]=a0.z; As[0][ak0+3][ar0]=a0.w;
        As[0][ak1+0][ar1]=a1.x; As[0][ak1+1][ar1]=a1.y; As[0][ak1+2][ar1]=a1.z; As[0][ak1+3][ar1]=a1.w;
        float4 b0 = *(const float4*)(g_bpad + (size_t)bk0*1024 + bcol + bc0);
        float4 b1 = *(const float4*)(g_bpad + (size_t)bk1*1024 + bcol + bc1);
        *(float4*)&Bs[0][bk0][bc0] = b0;
        *(float4*)&Bs[0][bk1][bc1] = b1;
    }
    __syncthreads();

    for (int t = 0; t < NT; t++){
        int cur = t & 1;
        float4 a0, a1, b0, b1;
        bool more = (t + 1 < NT);
        if (more){
            int k0 = (t+1) * 16;
            a0 = *(const float4*)(g_sin + (size_t)(brow + ar0)*SIN_LD + k0 + ak0);
            a1 = *(const float4*)(g_sin + (size_t)(brow + ar1)*SIN_LD + k0 + ak1);
            b0 = *(const float4*)(g_bpad + (size_t)(k0 + bk0)*1024 + bcol + bc0);
            b1 = *(const float4*)(g_bpad + (size_t)(k0 + bk1)*1024 + bcol + bc1);
        }
        #pragma unroll
        for (int kk = 0; kk < 16; kk++){
            float a[8], bb[8];
            #pragma unroll
            for (int x = 0; x < 8; x++) a[x]  = As[cur][kk][tr*8 + x];
            #pragma unroll
            for (int y = 0; y < 8; y++) bb[y] = Bs[cur][kk][tc*8 + y];
            #pragma unroll
            for (int x = 0; x < 8; x++)
                #pragma unroll
                for (int y = 0; y < 8; y++)
                    acc[x][y] += a[x] * bb[y];
        }
        if (more){
            int nxt = 1 - cur;
            As[nxt][ak0+0][ar0]=a0.x; As[nxt][ak0+1][ar0]=a0.y; As[nxt][ak0+2][ar0]=a0.z; As[nxt][ak0+3][ar0]=a0.w;
            As[nxt][ak1+0][ar1]=a1.x; As[nxt][ak1+1][ar1]=a1.y; As[nxt][ak1+2][ar1]=a1.z; As[nxt][ak1+3][ar1]=a1.w;
            *(float4*)&Bs[nxt][bk0][bc0] = b0;
            *(float4*)&Bs[nxt][bk1][bc1] = b1;
        }
        __syncthreads();
    }

    #pragma unroll
    for (int x = 0; x < 8; x++){
        int gr = brow + tr*8 + x;
        #pragma unroll
        for (int y4 = 0; y4 < 2; y4++){
            int gc = bcol + tc*8 + y4*4;
            float4 v;
            v.x = acc[x][y4*4+0] + bias[gc+0];
            v.y = acc[x][y4*4+1] + bias[gc+1];
            v.z = acc[x][y4*4+2] + bias[gc+2];
            v.w = acc[x][y4*4+3] + bias[gc+3];
            *(float4*)(g_spre + (size_t)gr*1024 + gc) = v;
        }
    }
}

/* ------------------------------------------------------------------ */
/* scalar layernorm + confidence RBF projection                        */
/* ------------------------------------------------------------------ */
__global__ void ln_conf_kernel(const float* __restrict__ conf,
                               const float* __restrict__ gam,
                               const float* __restrict__ bet,
                               const float* __restrict__ cw,
                               const float* __restrict__ cb,
                               float* __restrict__ ns)
{
    int nid = blockIdx.x, tid = threadIdx.x;
    __shared__ float red[8];
    __shared__ float sh_mu, sh_rstd;
    __shared__ float rbf[16];

    if (tid < 16){
        float c = conf[nid];
        float z = (c - (float)tid / 15.f) / 0.0625f;
        rbf[tid] = expf(-z*z);
    }

    const float* rp = g_spre + (size_t)nid*1024;
    float v[4];
    float lsum = 0.f;
    #pragma unroll
    for (int l = 0; l < 4; l++){ v[l] = rp[tid + l*256]; lsum += v[l]; }
    #pragma unroll
    for (int o = 16; o; o >>= 1) lsum += __shfl_down_sync(0xffffffffu, lsum, o);
    if ((tid & 31) == 0) red[tid >> 5] = lsum;
    __syncthreads();
    if (tid == 0){
        float s = 0.f;
        #pragma unroll
        for (int w = 0; w < 8; w++) s += red[w];
        sh_mu = s * (1.f/1024.f);
    }
    __syncthreads();
    float mu = sh_mu;
    float ls2 = 0.f;
    #pragma unroll
    for (int l = 0; l < 4; l++){ float d = v[l] - mu; ls2 += d*d; }
    #pragma unroll
    for (int o = 16; o; o >>= 1) ls2 += __shfl_down_sync(0xffffffffu, ls2, o);
    if ((tid & 31) == 0) red[tid >> 5] = ls2;
    __syncthreads();
    if (tid == 0){
        float s = 0.f;
        #pragma unroll
        for (int w = 0; w < 8; w++) s += red[w];
        sh_rstd = 1.f / sqrtf(s * (1.f/1024.f) + 1e-4f);
    }
    __syncthreads();
    float rstd = sh_rstd;
    #pragma unroll
    for (int l = 0; l < 4; l++){
        int j = tid + l*256;
        float add = 0.f;
        #pragma unroll
        for (int t = 0; t < 16; t++) add += rbf[t] * cw[t*1024 + j];
        ns[(size_t)nid*1024 + j] = (v[l] - mu) * rstd * gam[j] + bet[j] + add + cb[j];
    }
}

/* ------------------------------------------------------------------ */
/* edges — histogram-quantile top-30 + features + GVP + LN             */
/* one block (256 threads) per row; 8 candidates per thread            */
/* ------------------------------------------------------------------ */
__global__ void __launch_bounds__(256) edge_kernel(
                            const int* __restrict__ res_idx,
                            const float* __restrict__ ews,   /* (35,32) */
                            const float* __restrict__ ewb,
                            const float* __restrict__ eg,
                            const float* __restrict__ eb,
                            const float* __restrict__ ewh,
                            const float* __restrict__ ewv,
                            float* __restrict__ es_out,
                            float* __restrict__ ev_out,
                            float* __restrict__ ei_out)
{
    __shared__ unsigned int histp[8][256];      /* warp-private histograms */
    __shared__ unsigned int wsum[8];
    __shared__ unsigned long long clist[64];
    __shared__ int s_cnt;
    __shared__ int s_bin, s_lo, s_ceq;
    __shared__ float sfeat[KNN][36];
    __shared__ float espre[KNN][33];
    __shared__ float sevec[KNN][4];
    __shared__ float sW[35*32];

    int nid = blockIdx.x;
    int b = nid / L_, i = nid % L_;
    int tid = threadIdx.x;
    int wid = tid >> 5, lane = tid & 31;

    float4 ci = g_ca[nid];
    float xi = ci.x, yi = ci.y, zi = ci.z;
    bool mi = ci.w != 0.f;

    for (int f = tid; f < 35*32; f += 256) sW[f] = ews[f];

    /* keys: (f32_bits(D_adjust) << 32) | j  — identical math to R2/R3 */
    unsigned long long k[8];
    #pragma unroll
    for (int u = 0; u < 8; u++){
        int j = tid + u*256;
        float4 cj = g_ca[b*L_ + j];
        bool mj = cj.w != 0.f;
        int sd = abs(i - j);
        float val;
        if (mi && mj){
            if (sd <= 3) val = 0.f;
            else {
                float dx = __fadd_rn(xi, -cj.x);
                float dy = __fadd_rn(yi, -cj.y);
                float dz = __fadd_rn(zi, -cj.z);
                float s2 = __fadd_rn(__fadd_rn(__fadd_rn(__fmul_rn(dx,dx),
                                                          __fmul_rn(dy,dy)),
                                                __fmul_rn(dz,dz)), 1e-8f);
                val = sqrtf(s2);
            }
        } else {
            val = __fadd_rn(1e8f, __fmul_rn((float)sd, 1e6f));
        }
        k[u] = ((unsigned long long)__float_as_uint(val) << 32) | (unsigned)j;
    }

    /* byte-wise quantile refinement to isolate the 30th-smallest value */
    unsigned prefix = 0;
    int shift = 24;
    int lo = 0, ceq = 0;
    for (int level = 0; level < 4; level++){
        unsigned int* hflat = &histp[0][0];
        #pragma unroll
        for (int s = 0; s < 8; s++) hflat[tid + s*256] = 0;
        if (tid == 0) s_cnt = 0;
        __syncthreads();
        #pragma unroll
        for (int u = 0; u < 8; u++){
            unsigned v = (unsigned)(k[u] >> 32);
            bool match = (level == 0) || ((v >> (shift+8)) == (prefix >> (shift+8)));
            if (match) atomicAdd(&histp[wid][(v >> shift) & 0xFF], 1u);
        }
        __syncthreads();
        unsigned own = 0;
        #pragma unroll
        for (int w = 0; w < 8; w++) own += histp[w][tid];
        /* block inclusive scan over 256 bins */
        unsigned x = own;
        #pragma unroll
        for (int o = 1; o < 32; o <<= 1){
            unsigned y = __shfl_up_sync(0xffffffffu, x, o);
            if (lane >= o) x += y;
        }
        if (lane == 31) wsum[wid] = x;
        __syncthreads();
        if (wid == 0 && lane < 8){
            unsigned z = wsum[lane];
            #pragma unroll
            for (int o = 1; o < 8; o <<= 1){
                unsigned y = __shfl_up_sync(0xffu, z, o);
                if (lane >= o) z += y;
            }
            wsum[lane] = z;
        }
        __syncthreads();
        unsigned incl = x + (wid ? wsum[wid-1] : 0);
        unsigned excl = incl - own;
        if ((int)(lo + incl) >= KNN && (int)(lo + excl) < KNN){
            s_bin = tid; s_lo = lo + (int)excl; s_ceq = (int)own;
        }
        __syncthreads();
        prefix |= (unsigned)s_bin << shift;
        lo  = s_lo;
        ceq = s_ceq;
        if (lo + ceq <= 60 || shift == 0) break;
        shift -= 8;
        __syncthreads();   /* protect s_* before next level reuse */
    }

    /* collect all keys with truncated value <= boundary */
    if (tid < 64) clist[tid] = 0xFFFFFFFFFFFFFFFFULL;
    __syncthreads();
    unsigned bound = prefix >> shift;
    #pragma unroll
    for (int u = 0; u < 8; u++){
        unsigned v = (unsigned)(k[u] >> 32);
        if ((v >> shift) <= bound){
            int idx = atomicAdd(&s_cnt, 1);
            if (idx < 64) clist[idx] = k[u];
        }
    }
    __syncthreads();

    /* bitonic sort 64 (warp 0) */
    if (wid == 0){
        #pragma unroll
        for (int kk2 = 2; kk2 <= 64; kk2 <<= 1){
            for (int jj = kk2 >> 1; jj > 0; jj >>= 1){
                int ii = ((lane & ~(jj-1)) << 1) | (lane & (jj-1));
                int pp = ii | jj;
                bool up = ((ii & kk2) == 0);
                unsigned long long a = clist[ii], c = clist[pp];
                if ((a > c) == up){ clist[ii] = c; clist[pp] = a; }
                __syncwarp();
            }
        }
    }
    __syncthreads();

    /* scalar features for each selected edge */
    if (tid < KNN){
        int e = tid, j = (int)(clist[e] & 0xFFFFFFFFu);
        float4 cj = g_ca[b*L_ + j];
        bool mj = cj.w != 0.f;
        float dx = xi - cj.x, dy = yi - cj.y, dz = zi - cj.z;
        float dist = 0.f;
        if (mi && mj) dist = sqrtf(dx*dx + dy*dy + dz*dz + 1e-8f);
        #pragma unroll
        for (int t = 0; t < 16; t++){
            float c = (float)t * (20.f/15.f);
            float z = (dist - c) / 1.25f;
            sfeat[e][t] = expf(-z*z);
        }
        int dsi = res_idx[nid] - res_idx[b*L_ + j];
        float d = (float)max(-32, min(32, dsi));
        #pragma unroll
        for (int m8 = 0; m8 < 8; m8++){
            float fr = expf((float)(2*m8) * -0.5756462732485114f);
            float sv, cv; sincosf(d * fr, &sv, &cv);
            sfeat[e][16 + m8] = cv;
            sfeat[e][24 + m8] = sv;
        }
        sfeat[e][32] = mi ? 0.f : 1.f;
        sfeat[e][33] = mj ? 0.f : 1.f;
        float nrm = sqrtf(dx*dx + dy*dy + dz*dz + 1e-8f);
        float evx = dx/nrm, evy = dy/nrm, evz = dz/nrm;
        sevec[e][0] = evx; sevec[e][1] = evy; sevec[e][2] = evz;
        sevec[e][3] = (float)j;
        float whs = ewh[0];
        float vhx = evx*whs, vhy = evy*whs, vhz = evz*whs;
        sfeat[e][34] = sqrtf(fmaxf(vhx*vhx + vhy*vhy + vhz*vhz, 1e-8f));
    }
    __syncthreads();

    /* es_pre = sfeat @ W + b  (30x35 @ 35x32) */
    for (int idx = tid; idx < KNN*32; idx += 256){
        int e = idx >> 5, o = idx & 31;
        float s = ewb[o];
        #pragma unroll
        for (int f = 0; f < 35; f++) s += sfeat[e][f] * sW[f*32 + o];
        espre[e][o] = s;
    }
    __syncthreads();

    /* layernorm + vector output + edge index */
    if (tid < KNN){
        int e = tid;
        float mu = 0.f;
        #pragma unroll
        for (int o = 0; o < 32; o++) mu += espre[e][o];
        mu *= (1.f/32.f);
        float var = 0.f;
        #pragma unroll
        for (int o = 0; o < 32; o++){ float dd = espre[e][o] - mu; var += dd*dd; }
        var *= (1.f/32.f);
        float rstd = 1.f / sqrtf(var + 1e-4f);
        size_t gid = (size_t)nid * KNN + e;
        float* eo = es_out + gid*32;
        #pragma unroll
        for (int o = 0; o < 32; o++)
            eo[o] = (espre[e][o] - mu) * rstd * eg[o] + eb[o];

        float ww = ewh[0] * ewv[0];
        float vx = sevec[e][0]*ww, vy = sevec[e][1]*ww, vz = sevec[e][2]*ww;
        float dn = sqrtf(fmaxf(vx*vx + vy*vy + vz*vz, 1e-8f));
        float* vo = ev_out + gid*3;
        vo[0] = vx/dn; vo[1] = vy/dn; vo[2] = vz/dn;

        ei_out[gid]                 = (float)nid;
        ei_out[(size_t)NEDGE + gid] = (float)(b*L_ + (int)sevec[e][3]);
    }
}

/* ------------------------------------------------------------------ */
extern "C" void kernel_launch(void* const* d_in, const int* in_sizes, int n_in,
                              void* d_out, int out_size)
{
    const float*         coords     = (const float*)d_in[0];
    const unsigned char* cmask_raw  = (const unsigned char*)d_in[1];
    const int*           res_idx    = (const int*)d_in[2];
    const float*         confidence = (const float*)d_in[4];
    const float*         node_wh    = (const float*)d_in[5];
    const float*         node_ws_w  = (const float*)d_in[6];
    const float*         node_ws_b  = (const float*)d_in[7];
    const float*         node_wv    = (const float*)d_in[8];
    const float*         node_ln_g  = (const float*)d_in[9];
    const float*         node_ln_b  = (const float*)d_in[10];
    const float*         edge_wh    = (const float*)d_in[11];
    const float*         edge_ws_w  = (const float*)d_in[12];
    const float*         edge_ws_b  = (const float*)d_in[13];
    const float*         edge_wv    = (const float*)d_in[14];
    const float*         edge_ln_g  = (const float*)d_in[15];
    const float*         edge_ln_b  = (const float*)d_in[16];
    const float*         conf_w     = (const float*)d_in[17];
    const float*         conf_b     = (const float*)d_in[18];

    float* out = (float*)d_out;
    float* ns = out;
    float* nv = ns + (size_t)NNODE*1024;
    float* es = nv + (size_t)NNODE*256*3;
    float* ev = es + (size_t)NEDGE*32;
    float* ei = ev + (size_t)NEDGE*3;

    mask_prep_kernel<<<1, 1024>>>(cmask_raw);
    ca_pack_kernel<<<32, 256>>>(coords);
    prep_M_kernel<<<1, 256>>>(node_wh, node_wv);
    bpad_kernel<<<(KPAD*1024+255)/256, 256>>>(node_ws_w);
    geom_kernel<<<32, 256>>>(coords);
    node_main_kernel<<<NNODE, 256>>>(node_wh, nv);
    sgemm_kernel<<<dim3(8, 64), 256>>>(node_ws_b);
    ln_conf_kernel<<<NNODE, 256>>>(confidence, node_ln_g, node_ln_b, conf_w, conf_b, ns);
    edge_kernel<<<NNODE, 256>>>(res_idx,
                                edge_ws_w, edge_ws_b, edge_ln_g, edge_ln_b,
                                edge_wh, edge_wv, es, ev, ei);
    (void)in_sizes; (void)n_in; (void)out_size;
}

// round 5
// speedup vs baseline: 1.8579x; 1.0377x over previous
#include <cuda_runtime.h>
#include <math.h>

#define B_    4
#define L_    2048
#define KNN   30
#define NNODE (B_*L_)          /* 8192   */
#define NEDGE (NNODE*KNN)      /* 245760 */
#define SIN_LD 272             /* padded row stride for s_in (263 real + pad) */
#define KPAD  272

/* ------------------------------------------------------------------ */
/* static device scratch                                               */
/* ------------------------------------------------------------------ */
__device__ float g_M[768];                          /* wh @ wv  (3 x 256) */
__device__ float g_sin[(size_t)NNODE * SIN_LD];     /* GVP scalar input   */
__device__ float g_spre[(size_t)NNODE * 1024];      /* pre-LN scalar out  */
__device__ float4 g_ca[NNODE];                      /* CA xyz + mask flag  */
__device__ float g_geom[(size_t)NNODE * 16];        /* per-node geometry   */
__device__ float g_bpad[(size_t)KPAD * 1024];       /* padded B weights    */

struct F3 { float x, y, z; };
__device__ __forceinline__ F3 mkf3(float x, float y, float z){ F3 r; r.x=x; r.y=y; r.z=z; return r; }
__device__ __forceinline__ F3 sub3(F3 a, F3 b){ return mkf3(a.x-b.x, a.y-b.y, a.z-b.z); }
__device__ __forceinline__ F3 add3(F3 a, F3 b){ return mkf3(a.x+b.x, a.y+b.y, a.z+b.z); }
__device__ __forceinline__ float dot3(F3 a, F3 b){ return a.x*b.x + a.y*b.y + a.z*b.z; }
__device__ __forceinline__ F3 cross3(F3 a, F3 b){
    return mkf3(a.y*b.z - a.z*b.y, a.z*b.x - a.x*b.z, a.x*b.y - a.y*b.x);
}
__device__ __forceinline__ F3 norml(F3 a){
    float n = sqrtf(dot3(a,a) + 1e-8f);
    return mkf3(a.x/n, a.y/n, a.z/n);
}

/* ------------------------------------------------------------------ */
/* fused prep: mask-mode detect + CA pack + per-node geometry          */
/* 32 blocks x 256 threads; each block re-detects the bool layout      */
/* ------------------------------------------------------------------ */
__device__ __forceinline__ F3 ldatom(const float* Cb, int r, int a){
    const float* p = Cb + ((size_t)r*3 + a)*3;
    return mkf3(p[0], p[1], p[2]);
}

__global__ void prep_all_kernel(const float* __restrict__ coords,
                                const unsigned char* __restrict__ mraw)
{
    __shared__ int sA, sB;
    int tid = threadIdx.x;
    if (tid == 0){ sA = 0; sB = 0; }
    __syncthreads();
    int la = 0, lb = 0;
    for (int t = tid; t < 8192; t += 256){
        unsigned char v = mraw[t];
        if (v){
            if (t & 3) la++;
            else if ((t & 7) == 4) lb++;
        }
    }
    if (la) atomicAdd(&sA, la);
    if (lb) atomicAdd(&sB, lb);
    __syncthreads();
    int mode = (sA > 0) ? 0 : ((sB > 0) ? 1 : 2);   /* 0=byte 1=i32 2=i64 */

    int nid = blockIdx.x * 256 + tid;
    bool m;
    if (mode == 0)      m = mraw[nid] != 0;
    else if (mode == 1) m = ((const int*)mraw)[nid] != 0;
    else                m = ((const long long*)mraw)[nid] != 0;

    int b = nid / L_, i = nid % L_;
    const float* Cb = coords + (size_t)b * L_ * 9;

    /* CA pack */
    {
        const float* p = Cb + (size_t)i*9 + 3;
        float4 v; v.x = p[0]; v.y = p[1]; v.z = p[2]; v.w = m ? 1.f : 0.f;
        g_ca[nid] = v;
    }

    /* geometry */
    float* G = g_geom + (size_t)nid * 16;
    F3 xca = ldatom(Cb, i, 1);
    F3 fwd = mkf3(0.f,0.f,0.f), bk = mkf3(0.f,0.f,0.f);
    if (i < L_-1) fwd = norml(sub3(ldatom(Cb, i+1, 1), xca));
    if (i > 0)    bk  = norml(sub3(ldatom(Cb, i-1, 1), xca));
    F3 nn = norml(sub3(ldatom(Cb, i, 0), xca));
    F3 cc = norml(sub3(ldatom(Cb, i, 2), xca));
    F3 bis  = norml(add3(cc, nn));
    F3 perp = norml(cross3(cc, nn));
    const float k1 = 0.5773502691896258f;
    const float k2 = 0.8164965809277260f;
    F3 sc = mkf3(-bis.x*k1 - perp.x*k2, -bis.y*k1 - perp.y*k2, -bis.z*k1 - perp.z*k2);
    G[0]=fwd.x; G[1]=fwd.y; G[2]=fwd.z;
    G[3]=bk.x;  G[4]=bk.y;  G[5]=bk.z;
    G[6]=sc.x;  G[7]=sc.y;  G[8]=sc.z;

    F3 U[5];
    #pragma unroll
    for (int a = 0; a < 5; a++){
        int t = 3*i - 1 + a;
        if (t >= 0 && t <= 3*L_ - 2){
            F3 p0 = ldatom(Cb, t/3, t%3);
            int t1 = t + 1;
            F3 p1 = ldatom(Cb, t1/3, t1%3);
            U[a] = norml(sub3(p1, p0));
        } else U[a] = mkf3(0.f,0.f,0.f);
    }
    #pragma unroll
    for (int a = 0; a < 3; a++){
        int t = 3*i - 1 + a;
        float D = 0.f;
        if (t >= 0 && t <= 3*L_ - 4){
            F3 u2 = U[a], u1 = U[a+1], u0 = U[a+2];
            F3 n2 = norml(cross3(u2, u1));
            F3 n1 = norml(cross3(u1, u0));
            float cd = dot3(n2, n1);
            cd = fminf(fmaxf(cd, -1.f + 1e-7f), 1.f - 1e-7f);
            float sg = dot3(u2, n1);
            float s = (sg > 0.f) ? 1.f : ((sg < 0.f) ? -1.f : 0.f);
            D = s * acosf(cd);
        }
        G[9+a]  = cosf(D);
        G[12+a] = sinf(D);
    }
    G[15] = m ? 1.f : 0.f;
}

__global__ void prep_M_kernel(const float* __restrict__ wh, const float* __restrict__ wv){
    int v = threadIdx.x;
    #pragma unroll
    for (int i = 0; i < 3; i++){
        float s = 0.f;
        for (int h = 0; h < 256; h++) s += wh[i*256 + h] * wv[h*256 + v];
        g_M[i*256 + v] = s;
    }
}

__global__ void bpad_kernel(const float* __restrict__ Bw){
    int idx = blockIdx.x * 256 + threadIdx.x;
    if (idx >= KPAD*1024) return;
    int kk = idx >> 10, c = idx & 1023;
    g_bpad[idx] = (kk < 263) ? Bw[kk*1024 + c] : 0.f;
}

/* ------------------------------------------------------------------ */
/* GVP vector path + vector layernorm (block per node)                 */
/* ------------------------------------------------------------------ */
__global__ void node_main_kernel(const float* __restrict__ wh,
                                 float* __restrict__ nv_out)
{
    int nid = blockIdx.x;
    int tid = threadIdx.x;
    __shared__ float G[16];
    __shared__ float sh_red[8];
    __shared__ float sh_denom;

    if (tid < 16) G[tid] = g_geom[(size_t)nid*16 + tid];
    if (tid < 9)  g_sin[(size_t)nid*SIN_LD + 263 + tid] = 0.f;   /* K pad */
    __syncthreads();

    F3 v0 = mkf3(G[0], G[1], G[2]);
    F3 v1 = mkf3(G[3], G[4], G[5]);
    F3 v2 = mkf3(G[6], G[7], G[8]);

    int h = tid;
    float w0 = wh[h], w1 = wh[256+h], w2 = wh[512+h];
    F3 vh = mkf3(v0.x*w0 + v1.x*w1 + v2.x*w2,
                 v0.y*w0 + v1.y*w1 + v2.y*w2,
                 v0.z*w0 + v1.z*w1 + v2.z*w2);
    float vn = sqrtf(fmaxf(dot3(vh,vh), 1e-8f));
    g_sin[(size_t)nid*SIN_LD + 7 + h] = vn;
    if (tid < 7) g_sin[(size_t)nid*SIN_LD + tid] = G[9 + tid];

    float m0 = g_M[h], m1 = g_M[256+h], m2 = g_M[512+h];
    F3 vo = mkf3(v0.x*m0 + v1.x*m1 + v2.x*m2,
                 v0.y*m0 + v1.y*m1 + v2.y*m2,
                 v0.z*m0 + v1.z*m1 + v2.z*m2);
    float c = fmaxf(dot3(vo,vo), 1e-8f);
    #pragma unroll
    for (int o = 16; o; o >>= 1) c += __shfl_down_sync(0xffffffffu, c, o);
    if ((tid & 31) == 0) sh_red[tid >> 5] = c;
    __syncthreads();
    if (tid == 0){
        float s = 0.f;
        #pragma unroll
        for (int w = 0; w < 8; w++) s += sh_red[w];
        sh_denom = sqrtf(s * (1.f/256.f));
    }
    __syncthreads();
    float dn = sh_denom;
    float* o = nv_out + (size_t)nid*768 + (size_t)h*3;
    o[0] = vo.x/dn; o[1] = vo.y/dn; o[2] = vo.z/dn;
}

/* ------------------------------------------------------------------ */
/* SGEMM  C[8192,1024] = A[8192,272p] @ Bpad[272,1024] + bias          */
/* ------------------------------------------------------------------ */
__global__ void __launch_bounds__(256) sgemm_kernel(const float* __restrict__ bias)
{
    const int NT = KPAD / 16;             /* 17 */
    __shared__ float As[2][16][132];
    __shared__ float Bs[2][16][128];
    int tid = threadIdx.x;
    int brow = blockIdx.y * 128, bcol = blockIdx.x * 128;
    int tr = tid / 16, tc = tid % 16;

    float acc[8][8];
    #pragma unroll
    for (int x = 0; x < 8; x++)
        #pragma unroll
        for (int y = 0; y < 8; y++) acc[x][y] = 0.f;

    int aq0 = tid, aq1 = tid + 256;
    int ar0 = aq0 >> 2, ak0 = (aq0 & 3) * 4;
    int ar1 = aq1 >> 2, ak1 = (aq1 & 3) * 4;
    int bk0 = tid >> 5, bc0 = (tid & 31) * 4;
    int bk1 = (tid + 256) >> 5, bc1 = (tid & 31) * 4;

    {
        float4 a0 = *(const float4*)(g_sin + (size_t)(brow + ar0)*SIN_LD + ak0);
        float4 a1 = *(const float4*)(g_sin + (size_t)(brow + ar1)*SIN_LD + ak1);
        As[0][ak0+0][ar0]=a0.x; As[0][ak0+1][ar0]=a0.y; As[0][ak0+2][ar0]=a0.z; As[0][ak0+3][ar0]=a0.w;
        As[0][ak1+0][ar1]=a1.x; As[0][ak1+1][ar1]=a1.y; As[0][ak1+2][ar1]=a1.z; As[0][ak1+3][ar1]=a1.w;
        float4 b0 = *(const float4*)(g_bpad + (size_t)bk0*1024 + bcol + bc0);
        float4 b1 = *(const float4*)(g_bpad + (size_t)bk1*1024 + bcol + bc1);
        *(float4*)&Bs[0][bk0][bc0] = b0;
        *(float4*)&Bs[0][bk1][bc1] = b1;
    }
    __syncthreads();

    for (int t = 0; t < NT; t++){
        int cur = t & 1;
        float4 a0, a1, b0, b1;
        bool more = (t + 1 < NT);
        if (more){
            int k0 = (t+1) * 16;
            a0 = *(const float4*)(g_sin + (size_t)(brow + ar0)*SIN_LD + k0 + ak0);
            a1 = *(const float4*)(g_sin + (size_t)(brow + ar1)*SIN_LD + k0 + ak1);
            b0 = *(const float4*)(g_bpad + (size_t)(k0 + bk0)*1024 + bcol + bc0);
            b1 = *(const float4*)(g_bpad + (size_t)(k0 + bk1)*1024 + bcol + bc1);
        }
        #pragma unroll
        for (int kk = 0; kk < 16; kk++){
            float a[8], bb[8];
            #pragma unroll
            for (int x = 0; x < 8; x++) a[x]  = As[cur][kk][tr*8 + x];
            #pragma unroll
            for (int y = 0; y < 8; y++) bb[y] = Bs[cur][kk][tc*8 + y];
            #pragma unroll
            for (int x = 0; x < 8; x++)
                #pragma unroll
                for (int y = 0; y < 8; y++)
                    acc[x][y] += a[x] * bb[y];
        }
        if (more){
            int nxt = 1 - cur;
            As[nxt][ak0+0][ar0]=a0.x; As[nxt][ak0+1][ar0]=a0.y; As[nxt][ak0+2][ar0]=a0.z; As[nxt][ak0+3][ar0]=a0.w;
            As[nxt][ak1+0][ar1]=a1.x; As[nxt][ak1+1][ar1]=a1.y; As[nxt][ak1+2][ar1]=a1.z; As[nxt][ak1+3][ar1]=a1.w;
            *(float4*)&Bs[nxt][bk0][bc0] = b0;
            *(float4*)&Bs[nxt][bk1][bc1] = b1;
        }
        __syncthreads();
    }

    #pragma unroll
    for (int x = 0; x < 8; x++){
        int gr = brow + tr*8 + x;
        #pragma unroll
        for (int y4 = 0; y4 < 2; y4++){
            int gc = bcol + tc*8 + y4*4;
            float4 v;
            v.x = acc[x][y4*4+0] + bias[gc+0];
            v.y = acc[x][y4*4+1] + bias[gc+1];
            v.z = acc[x][y4*4+2] + bias[gc+2];
            v.w = acc[x][y4*4+3] + bias[gc+3];
            *(float4*)(g_spre + (size_t)gr*1024 + gc) = v;
        }
    }
}

/* ------------------------------------------------------------------ */
/* scalar layernorm + confidence RBF projection                        */
/* ------------------------------------------------------------------ */
__global__ void ln_conf_kernel(const float* __restrict__ conf,
                               const float* __restrict__ gam,
                               const float* __restrict__ bet,
                               const float* __restrict__ cw,
                               const float* __restrict__ cb,
                               float* __restrict__ ns)
{
    int nid = blockIdx.x, tid = threadIdx.x;
    __shared__ float red[8];
    __shared__ float sh_mu, sh_rstd;
    __shared__ float rbf[16];

    if (tid < 16){
        float c = conf[nid];
        float z = (c - (float)tid / 15.f) / 0.0625f;
        rbf[tid] = expf(-z*z);
    }

    const float* rp = g_spre + (size_t)nid*1024;
    float v[4];
    float lsum = 0.f;
    #pragma unroll
    for (int l = 0; l < 4; l++){ v[l] = rp[tid + l*256]; lsum += v[l]; }
    #pragma unroll
    for (int o = 16; o; o >>= 1) lsum += __shfl_down_sync(0xffffffffu, lsum, o);
    if ((tid & 31) == 0) red[tid >> 5] = lsum;
    __syncthreads();
    if (tid == 0){
        float s = 0.f;
        #pragma unroll
        for (int w = 0; w < 8; w++) s += red[w];
        sh_mu = s * (1.f/1024.f);
    }
    __syncthreads();
    float mu = sh_mu;
    float ls2 = 0.f;
    #pragma unroll
    for (int l = 0; l < 4; l++){ float d = v[l] - mu; ls2 += d*d; }
    #pragma unroll
    for (int o = 16; o; o >>= 1) ls2 += __shfl_down_sync(0xffffffffu, ls2, o);
    if ((tid & 31) == 0) red[tid >> 5] = ls2;
    __syncthreads();
    if (tid == 0){
        float s = 0.f;
        #pragma unroll
        for (int w = 0; w < 8; w++) s += red[w];
        sh_rstd = 1.f / sqrtf(s * (1.f/1024.f) + 1e-4f);
    }
    __syncthreads();
    float rstd = sh_rstd;
    #pragma unroll
    for (int l = 0; l < 4; l++){
        int j = tid + l*256;
        float add = 0.f;
        #pragma unroll
        for (int t = 0; t < 16; t++) add += rbf[t] * cw[t*1024 + j];
        ns[(size_t)nid*1024 + j] = (v[l] - mu) * rstd * gam[j] + bet[j] + add + cb[j];
    }
}

/* ------------------------------------------------------------------ */
/* edges — histogram-quantile top-30 + features + GVP + LN             */
/* ------------------------------------------------------------------ */
__global__ void __launch_bounds__(256) edge_kernel(
                            const int* __restrict__ res_idx,
                            const float* __restrict__ ews,
                            const float* __restrict__ ewb,
                            const float* __restrict__ eg,
                            const float* __restrict__ eb,
                            const float* __restrict__ ewh,
                            const float* __restrict__ ewv,
                            float* __restrict__ es_out,
                            float* __restrict__ ev_out,
                            float* __restrict__ ei_out)
{
    __shared__ unsigned int histp[8][256];
    __shared__ unsigned int wsum[8];
    __shared__ unsigned long long clist[64];
    __shared__ int s_cnt;
    __shared__ int s_bin, s_lo, s_ceq;
    __shared__ float sfeat[KNN][36];
    __shared__ float espre[KNN][33];
    __shared__ float sevec[KNN][4];
    __shared__ float sW[35*32];

    int nid = blockIdx.x;
    int b = nid / L_, i = nid % L_;
    int tid = threadIdx.x;
    int wid = tid >> 5, lane = tid & 31;

    float4 ci = g_ca[nid];
    float xi = ci.x, yi = ci.y, zi = ci.z;
    bool mi = ci.w != 0.f;

    for (int f = tid; f < 35*32; f += 256) sW[f] = ews[f];

    unsigned long long k[8];
    #pragma unroll
    for (int u = 0; u < 8; u++){
        int j = tid + u*256;
        float4 cj = g_ca[b*L_ + j];
        bool mj = cj.w != 0.f;
        int sd = abs(i - j);
        float val;
        if (mi && mj){
            if (sd <= 3) val = 0.f;
            else {
                float dx = __fadd_rn(xi, -cj.x);
                float dy = __fadd_rn(yi, -cj.y);
                float dz = __fadd_rn(zi, -cj.z);
                float s2 = __fadd_rn(__fadd_rn(__fadd_rn(__fmul_rn(dx,dx),
                                                          __fmul_rn(dy,dy)),
                                                __fmul_rn(dz,dz)), 1e-8f);
                val = sqrtf(s2);
            }
        } else {
            val = __fadd_rn(1e8f, __fmul_rn((float)sd, 1e6f));
        }
        k[u] = ((unsigned long long)__float_as_uint(val) << 32) | (unsigned)j;
    }

    /* byte-wise quantile refinement */
    unsigned prefix = 0;
    int shift = 24;
    int lo = 0, ceq = 0;
    for (int level = 0; level < 4; level++){
        unsigned int* hflat = &histp[0][0];
        #pragma unroll
        for (int s = 0; s < 8; s++) hflat[tid + s*256] = 0;
        if (tid == 0) s_cnt = 0;
        __syncthreads();
        #pragma unroll
        for (int u = 0; u < 8; u++){
            unsigned v = (unsigned)(k[u] >> 32);
            bool match = (level == 0) || ((v >> (shift+8)) == (prefix >> (shift+8)));
            if (match) atomicAdd(&histp[wid][(v >> shift) & 0xFF], 1u);
        }
        __syncthreads();
        unsigned own = 0;
        #pragma unroll
        for (int w = 0; w < 8; w++) own += histp[w][tid];
        unsigned x = own;
        #pragma unroll
        for (int o = 1; o < 32; o <<= 1){
            unsigned y = __shfl_up_sync(0xffffffffu, x, o);
            if (lane >= o) x += y;
        }
        if (lane == 31) wsum[wid] = x;
        __syncthreads();
        if (wid == 0 && lane < 8){
            unsigned z = wsum[lane];
            #pragma unroll
            for (int o = 1; o < 8; o <<= 1){
                unsigned y = __shfl_up_sync(0xffu, z, o);
                if (lane >= o) z += y;
            }
            wsum[lane] = z;
        }
        __syncthreads();
        unsigned incl = x + (wid ? wsum[wid-1] : 0);
        unsigned excl = incl - own;
        if ((int)(lo + incl) >= KNN && (int)(lo + excl) < KNN){
            s_bin = tid; s_lo = lo + (int)excl; s_ceq = (int)own;
        }
        __syncthreads();
        prefix |= (unsigned)s_bin << shift;
        lo  = s_lo;
        ceq = s_ceq;
        if (lo + ceq <= 60 || shift == 0) break;
        shift -= 8;
        __syncthreads();
    }

    if (tid < 64) clist[tid] = 0xFFFFFFFFFFFFFFFFULL;
    __syncthreads();
    unsigned bound = prefix >> shift;
    #pragma unroll
    for (int u = 0; u < 8; u++){
        unsigned v = (unsigned)(k[u] >> 32);
        if ((v >> shift) <= bound){
            int idx = atomicAdd(&s_cnt, 1);
            if (idx < 64) clist[idx] = k[u];
        }
    }
    __syncthreads();

    if (wid == 0){
        #pragma unroll
        for (int kk2 = 2; kk2 <= 64; kk2 <<= 1){
            for (int jj = kk2 >> 1; jj > 0; jj >>= 1){
                int ii = ((lane & ~(jj-1)) << 1) | (lane & (jj-1));
                int pp = ii | jj;
                bool up = ((ii & kk2) == 0);
                unsigned long long a = clist[ii], c = clist[pp];
                if ((a > c) == up){ clist[ii] = c; clist[pp] = a; }
                __syncwarp();
            }
        }
    }
    __syncthreads();

    if (tid < KNN){
        int e = tid, j = (int)(clist[e] & 0xFFFFFFFFu);
        float4 cj = g_ca[b*L_ + j];
        bool mj = cj.w != 0.f;
        float dx = xi - cj.x, dy = yi - cj.y, dz = zi - cj.z;
        float dist = 0.f;
        if (mi && mj) dist = sqrtf(dx*dx + dy*dy + dz*dz + 1e-8f);
        #pragma unroll
        for (int t = 0; t < 16; t++){
            float c = (float)t * (20.f/15.f);
            float z = (dist - c) / 1.25f;
            sfeat[e][t] = expf(-z*z);
        }
        int dsi = res_idx[nid] - res_idx[b*L_ + j];
        float d = (float)max(-32, min(32, dsi));
        #pragma unroll
        for (int m8 = 0; m8 < 8; m8++){
            float fr = expf((float)(2*m8) * -0.5756462732485114f);
            float sv, cv; sincosf(d * fr, &sv, &cv);
            sfeat[e][16 + m8] = cv;
            sfeat[e][24 + m8] = sv;
        }
        sfeat[e][32] = mi ? 0.f : 1.f;
        sfeat[e][33] = mj ? 0.f : 1.f;
        float nrm = sqrtf(dx*dx + dy*dy + dz*dz + 1e-8f);
        float evx = dx/nrm, evy = dy/nrm, evz = dz/nrm;
        sevec[e][0] = evx; sevec[e][1] = evy; sevec[e][2] = evz;
        sevec[e][3] = (float)j;
        float whs = ewh[0];
        float vhx = evx*whs, vhy = evy*whs, vhz = evz*whs;
        sfeat[e][34] = sqrtf(fmaxf(vhx*vhx + vhy*vhy + vhz*vhz, 1e-8f));
    }
    __syncthreads();

    for (int idx = tid; idx < KNN*32; idx += 256){
        int e = idx >> 5, o = idx & 31;
        float s = ewb[o];
        #pragma unroll
        for (int f = 0; f < 35; f++) s += sfeat[e][f] * sW[f*32 + o];
        espre[e][o] = s;
    }
    __syncthreads();

    if (tid < KNN){
        int e = tid;
        float mu = 0.f;
        #pragma unroll
        for (int o = 0; o < 32; o++) mu += espre[e][o];
        mu *= (1.f/32.f);
        float var = 0.f;
        #pragma unroll
        for (int o = 0; o < 32; o++){ float dd = espre[e][o] - mu; var += dd*dd; }
        var *= (1.f/32.f);
        float rstd = 1.f / sqrtf(var + 1e-4f);
        size_t gid = (size_t)nid * KNN + e;
        float* eo = es_out + gid*32;
        #pragma unroll
        for (int o = 0; o < 32; o++)
            eo[o] = (espre[e][o] - mu) * rstd * eg[o] + eb[o];

        float ww = ewh[0] * ewv[0];
        float vx = sevec[e][0]*ww, vy = sevec[e][1]*ww, vz = sevec[e][2]*ww;
        float dn = sqrtf(fmaxf(vx*vx + vy*vy + vz*vz, 1e-8f));
        float* vo = ev_out + gid*3;
        vo[0] = vx/dn; vo[1] = vy/dn; vo[2] = vz/dn;

        ei_out[gid]                 = (float)nid;
        ei_out[(size_t)NEDGE + gid] = (float)(b*L_ + (int)sevec[e][3]);
    }
}

/* ------------------------------------------------------------------ */
extern "C" void kernel_launch(void* const* d_in, const int* in_sizes, int n_in,
                              void* d_out, int out_size)
{
    const float*         coords     = (const float*)d_in[0];
    const unsigned char* cmask_raw  = (const unsigned char*)d_in[1];
    const int*           res_idx    = (const int*)d_in[2];
    const float*         confidence = (const float*)d_in[4];
    const float*         node_wh    = (const float*)d_in[5];
    const float*         node_ws_w  = (const float*)d_in[6];
    const float*         node_ws_b  = (const float*)d_in[7];
    const float*         node_wv    = (const float*)d_in[8];
    const float*         node_ln_g  = (const float*)d_in[9];
    const float*         node_ln_b  = (const float*)d_in[10];
    const float*         edge_wh    = (const float*)d_in[11];
    const float*         edge_ws_w  = (const float*)d_in[12];
    const float*         edge_ws_b  = (const float*)d_in[13];
    const float*         edge_wv    = (const float*)d_in[14];
    const float*         edge_ln_g  = (const float*)d_in[15];
    const float*         edge_ln_b  = (const float*)d_in[16];
    const float*         conf_w     = (const float*)d_in[17];
    const float*         conf_b     = (const float*)d_in[18];

    float* out = (float*)d_out;
    float* ns = out;
    float* nv = ns + (size_t)NNODE*1024;
    float* es = nv + (size_t)NNODE*256*3;
    float* ev = es + (size_t)NEDGE*32;
    float* ei = ev + (size_t)NEDGE*3;

    /* shared prep (default stream) */
    prep_all_kernel<<<32, 256>>>(coords, cmask_raw);
    prep_M_kernel<<<1, 256>>>(node_wh, node_wv);
    bpad_kernel<<<(KPAD*1024+255)/256, 256>>>(node_ws_w);

    /* fork: edge chain on side stream, node chain on default stream */
    cudaStream_t s1;
    cudaStreamCreateWithFlags(&s1, cudaStreamNonBlocking);
    cudaEvent_t ev0, ev1;
    cudaEventCreateWithFlags(&ev0, cudaEventDisableTiming);
    cudaEventCreateWithFlags(&ev1, cudaEventDisableTiming);

    cudaEventRecord(ev0, 0);
    cudaStreamWaitEvent(s1, ev0, 0);
    edge_kernel<<<NNODE, 256, 0, s1>>>(res_idx,
                                edge_ws_w, edge_ws_b, edge_ln_g, edge_ln_b,
                                edge_wh, edge_wv, es, ev, ei);
    cudaEventRecord(ev1, s1);

    node_main_kernel<<<NNODE, 256>>>(node_wh, nv);
    sgemm_kernel<<<dim3(8, 64), 256>>>(node_ws_b);
    ln_conf_kernel<<<NNODE, 256>>>(confidence, node_ln_g, node_ln_b, conf_w, conf_b, ns);

    cudaStreamWaitEvent(0, ev1, 0);   /* join */

    cudaEventDestroy(ev0);
    cudaEventDestroy(ev1);
    cudaStreamDestroy(s1);
    (void)in_sizes; (void)n_in; (void)out_size;
}